// round 12
// baseline (speedup 1.0000x reference)
#include <cuda_runtime.h>
#include <cuda_bf16.h>
#include <cuda_fp16.h>
#include <math.h>
#include <math_constants.h>
#include <cstdint>

#define Nn   50000
#define Ee   800000
#define DD   256
#define EDD  128
#define Hh   4

typedef __nv_bfloat16 bf16;
typedef unsigned long long u64;

// ================= scratch (device globals) =================
__device__ __half g_q[Nn * DD];
__device__ __half g_k[Nn * DD];
__device__ __half g_v[Nn * DD];
__device__ float  g_h[Nn * DD];
__device__ __half g_e1[(size_t)Ee * DD];
__device__ __half g_e2[(size_t)Ee * DD];
// CSR for dst-grouped edges
__device__ int g_deg[Nn];
__device__ int g_cursor[Nn];
__device__ int g_loc[Nn];
__device__ int g_bsum[256];
__device__ int g_rowptr[Nn + 1];
__device__ int g_adj[Ee];
__device__ int g_srcp[Ee];
// operands
__device__ bf16 g_xhi[Nn * DD], g_xlo[Nn * DD];
__device__ __half g_xf16[Nn * DD];
__device__ __half g_eaf16[(size_t)Ee * EDD];
__device__ bf16 g_whi[2 * 65536], g_wlo[2 * 65536];
__device__ __half g_wqkv16[2 * 768 * 256];
__device__ __half g_wef16[2 * 256 * 128];

// ================= PTX helpers =================
__device__ __forceinline__ uint32_t smem_u32(const void* p) {
    uint32_t a;
    asm("{ .reg .u64 t; cvta.to.shared.u64 t, %1; cvt.u32.u64 %0, t; }"
        : "=r"(a) : "l"(p));
    return a;
}
__device__ __forceinline__ void ldsm_x4(uint32_t* r, uint32_t a) {
    asm volatile("ldmatrix.sync.aligned.m8n8.x4.shared.b16 {%0,%1,%2,%3}, [%4];"
        : "=r"(r[0]), "=r"(r[1]), "=r"(r[2]), "=r"(r[3]) : "r"(a));
}
__device__ __forceinline__ void ldsm_x2(uint32_t* r, uint32_t a) {
    asm volatile("ldmatrix.sync.aligned.m8n8.x2.shared.b16 {%0,%1}, [%2];"
        : "=r"(r[0]), "=r"(r[1]) : "r"(a));
}
__device__ __forceinline__ void mma_bf16(float* d, const uint32_t* a, const uint32_t* b) {
    asm volatile("mma.sync.aligned.m16n8k16.row.col.f32.bf16.bf16.f32 "
        "{%0,%1,%2,%3}, {%4,%5,%6,%7}, {%8,%9}, {%0,%1,%2,%3};"
        : "+f"(d[0]), "+f"(d[1]), "+f"(d[2]), "+f"(d[3])
        : "r"(a[0]), "r"(a[1]), "r"(a[2]), "r"(a[3]), "r"(b[0]), "r"(b[1]));
}
__device__ __forceinline__ void mma_f16(float* d, const uint32_t* a, const uint32_t* b) {
    asm volatile("mma.sync.aligned.m16n8k16.row.col.f32.f16.f16.f32 "
        "{%0,%1,%2,%3}, {%4,%5,%6,%7}, {%8,%9}, {%0,%1,%2,%3};"
        : "+f"(d[0]), "+f"(d[1]), "+f"(d[2]), "+f"(d[3])
        : "r"(a[0]), "r"(a[1]), "r"(a[2]), "r"(a[3]), "r"(b[0]), "r"(b[1]));
}
__device__ __forceinline__ void cpa16(uint32_t dst, const void* src, int sz) {
    asm volatile("cp.async.cg.shared.global [%0], [%1], 16, %2;"
        :: "r"(dst), "l"(src), "r"(sz) : "memory");
}
#define CP_COMMIT() asm volatile("cp.async.commit_group;" ::: "memory")
#define CP_WAIT1()  asm volatile("cp.async.wait_group 1;" ::: "memory")
#define CP_WAIT0()  asm volatile("cp.async.wait_group 0;" ::: "memory")

// ---- packed f32x2 ops (sm_103a FFMA2 path) ----
__device__ __forceinline__ u64 f2_pack(float x, float y) {
    u64 r;
    asm("mov.b64 %0, {%1, %2};" : "=l"(r)
        : "r"(__float_as_uint(x)), "r"(__float_as_uint(y)));
    return r;
}
__device__ __forceinline__ float2 f2_unpack(u64 p) {
    uint32_t lo, hi;
    asm("mov.b64 {%0, %1}, %2;" : "=r"(lo), "=r"(hi) : "l"(p));
    return make_float2(__uint_as_float(lo), __uint_as_float(hi));
}
__device__ __forceinline__ u64 f2_add(u64 a, u64 b) {
    u64 r; asm("add.rn.f32x2 %0, %1, %2;" : "=l"(r) : "l"(a), "l"(b)); return r;
}
__device__ __forceinline__ u64 f2_mul(u64 a, u64 b) {
    u64 r; asm("mul.rn.f32x2 %0, %1, %2;" : "=l"(r) : "l"(a), "l"(b)); return r;
}
__device__ __forceinline__ u64 f2_fma(u64 a, u64 b, u64 c) {
    u64 r; asm("fma.rn.f32x2 %0, %1, %2, %3;" : "=l"(r) : "l"(a), "l"(b), "l"(c));
    return r;
}
// 8 halves -> 4 packed f32x2
__device__ __forceinline__ void cvt4p(u64* o, uint4 u) {
    const __half2* h = (const __half2*)&u;
    #pragma unroll
    for (int i = 0; i < 4; i++) {
        float2 t = __half22float2(h[i]);
        o[i] = f2_pack(t.x, t.y);
    }
}

// ================= bf16x3 pipelined GEMM (skip path S only) =============
#define PAD 40
#define STG_B 40960
#define OFF_AL 10240
#define OFF_BH 20480
#define OFF_BL 30720
#define GEMM_SMEM (2 * STG_B)

__global__ __launch_bounds__(256, 2) void gemm_bf3(
    int M, int K,
    const bf16* __restrict__ Ahi, const bf16* __restrict__ Alo,
    const bf16* __restrict__ Whi, const bf16* __restrict__ Wlo,
    float* __restrict__ Cf, const float* __restrict__ bias)
{
    extern __shared__ char sm[];
    const uint32_t sb = smem_u32(sm);

    const int tid  = threadIdx.x;
    const int lane = tid & 31;
    const int wid  = tid >> 5;
    const int wm   = wid >> 2;
    const int wn   = wid & 3;
    const int row0 = blockIdx.y * 128;
    const int nW0  = blockIdx.x * 128;
    const int colb = blockIdx.x * 128;

    const int lr  = tid >> 1;
    const int lcb = (tid & 1) * 16;
    const int grA  = row0 + lr;
    const int okA  = (grA < M) ? 16 : 0;
    const int arow = okA ? grA : 0;
    const size_t aoff = (size_t)arow * K + lcb;
    const size_t boff = (size_t)(nW0 + lr) * K + lcb;
    const char* pAh = (const char*)(Ahi + aoff);
    const char* pAl = (const char*)(Alo + aoff);
    const char* pBh = (const char*)(Whi + boff);
    const char* pBl = (const char*)(Wlo + boff);
    const uint32_t dstA = sb + (uint32_t)(lr * 80 + (tid & 1) * 32);

    const int nchunk = K >> 5;

    const int aRow    = lane & 15;
    const int aColSel = (lane >> 4) * 8;
    const int bRow    = lane & 7;
    const int bColSel = ((lane >> 3) & 1) * 8;

    float acc[4][4][4];
    #pragma unroll
    for (int i = 0; i < 4; i++)
        #pragma unroll
        for (int j = 0; j < 4; j++)
            #pragma unroll
            for (int t = 0; t < 4; t++) acc[i][j][t] = 0.f;

    {
        cpa16(dstA,               pAh,      okA);
        cpa16(dstA + 16,          pAh + 16, okA);
        cpa16(dstA + OFF_AL,      pAl,      okA);
        cpa16(dstA + OFF_AL + 16, pAl + 16, okA);
        cpa16(dstA + OFF_BH,      pBh,      16);
        cpa16(dstA + OFF_BH + 16, pBh + 16, 16);
        cpa16(dstA + OFF_BL,      pBl,      16);
        cpa16(dstA + OFF_BL + 16, pBl + 16, 16);
        CP_COMMIT();
    }

    for (int c = 0; c < nchunk; c++) {
        if (c + 1 < nchunk) {
            const uint32_t d = dstA + ((c + 1) & 1) * STG_B;
            const int go = (c + 1) * 64;
            cpa16(d,               pAh + go,      okA);
            cpa16(d + 16,          pAh + go + 16, okA);
            cpa16(d + OFF_AL,      pAl + go,      okA);
            cpa16(d + OFF_AL + 16, pAl + go + 16, okA);
            cpa16(d + OFF_BH,      pBh + go,      16);
            cpa16(d + OFF_BH + 16, pBh + go + 16, 16);
            cpa16(d + OFF_BL,      pBl + go,      16);
            cpa16(d + OFF_BL + 16, pBl + go + 16, 16);
            CP_COMMIT();
            CP_WAIT1();
        } else {
            CP_WAIT0();
        }
        __syncthreads();

        const uint32_t sbase = sb + (c & 1) * STG_B;
        #pragma unroll
        for (int ks = 0; ks < 2; ks++) {
            const int kb = ks * 16;
            uint32_t ah[4][4], al[4][4], bh[4][2], bl[4][2];
            #pragma unroll
            for (int mt = 0; mt < 4; mt++) {
                const uint32_t off = sbase +
                    (uint32_t)((wm * 64 + mt * 16 + aRow) * PAD + kb + aColSel) * 2;
                ldsm_x4(ah[mt], off);
                ldsm_x4(al[mt], off + OFF_AL);
            }
            #pragma unroll
            for (int nt = 0; nt < 4; nt++) {
                const uint32_t off = sbase + OFF_BH +
                    (uint32_t)((wn * 32 + nt * 8 + bRow) * PAD + kb + bColSel) * 2;
                ldsm_x2(bh[nt], off);
                ldsm_x2(bl[nt], off + (OFF_BL - OFF_BH));
            }
            #pragma unroll
            for (int mt = 0; mt < 4; mt++)
                #pragma unroll
                for (int nt = 0; nt < 4; nt++) {
                    mma_bf16(acc[mt][nt], ah[mt], bh[nt]);
                    mma_bf16(acc[mt][nt], ah[mt], bl[nt]);
                    mma_bf16(acc[mt][nt], al[mt], bh[nt]);
                }
        }
        __syncthreads();
    }

    #pragma unroll
    for (int mt = 0; mt < 4; mt++) {
        const int r = row0 + wm * 64 + mt * 16 + (lane >> 2);
        #pragma unroll
        for (int nt = 0; nt < 4; nt++) {
            const int c = colb + wn * 32 + nt * 8 + (lane & 3) * 2;
            if (r < M) {
                float2 o = make_float2(acc[mt][nt][0] + bias[c],
                                       acc[mt][nt][1] + bias[c + 1]);
                *(float2*)(Cf + (size_t)r * 256 + c) = o;
            }
            if (r + 8 < M) {
                float2 o = make_float2(acc[mt][nt][2] + bias[c],
                                       acc[mt][nt][3] + bias[c + 1]);
                *(float2*)(Cf + (size_t)(r + 8) * 256 + c) = o;
            }
        }
    }
}

// ============ single-pass fp16 GEMM, up to 3 routed fp16 outputs ============
#define STG_F 20480
#define OFF_FB 10240
#define GEMMF_SMEM (2 * STG_F)

__global__ __launch_bounds__(256, 2) void gemm_f16(
    int M, int K,
    const __half* __restrict__ A, const __half* __restrict__ W,
    const int* __restrict__ rowmap,
    __half* c0, __half* c1, __half* c2,
    const float* b0, const float* b1, const float* b2)
{
    extern __shared__ char sm[];
    const uint32_t sb = smem_u32(sm);

    const int tid  = threadIdx.x;
    const int lane = tid & 31;
    const int wid  = tid >> 5;
    const int wm   = wid >> 2;
    const int wn   = wid & 3;
    const int row0 = blockIdx.y * 128;

    __half* const outs[3]        = { c0, c1, c2 };
    const float* const biases[3] = { b0, b1, b2 };
    const int    outIdx = blockIdx.x >> 1;
    __half*      C    = outs[outIdx];
    const float* bias = biases[outIdx];
    const int    colb = (blockIdx.x & 1) * 128;
    const int    nW0  = outIdx * 256 + colb;

    const int lr  = tid >> 1;
    const int lcb = (tid & 1) * 16;
    const int grA = row0 + lr;
    const int okA = (grA < M) ? 16 : 0;
    int arow = okA ? grA : 0;
    if (rowmap) arow = rowmap[arow];
    const char* pA = (const char*)(A + (size_t)arow * K + lcb);
    const char* pB = (const char*)(W + (size_t)(nW0 + lr) * K + lcb);
    const uint32_t dstA = sb + (uint32_t)(lr * 80 + (tid & 1) * 32);

    const int nchunk = K >> 5;

    const int aRow    = lane & 15;
    const int aColSel = (lane >> 4) * 8;
    const int bRow    = lane & 7;
    const int bColSel = ((lane >> 3) & 1) * 8;

    float acc[4][4][4];
    #pragma unroll
    for (int i = 0; i < 4; i++)
        #pragma unroll
        for (int j = 0; j < 4; j++)
            #pragma unroll
            for (int t = 0; t < 4; t++) acc[i][j][t] = 0.f;

    {
        cpa16(dstA,                pA,      okA);
        cpa16(dstA + 16,           pA + 16, okA);
        cpa16(dstA + OFF_FB,       pB,      16);
        cpa16(dstA + OFF_FB + 16,  pB + 16, 16);
        CP_COMMIT();
    }

    for (int c = 0; c < nchunk; c++) {
        if (c + 1 < nchunk) {
            const uint32_t d = dstA + ((c + 1) & 1) * STG_F;
            const int go = (c + 1) * 64;
            cpa16(d,               pA + go,      okA);
            cpa16(d + 16,          pA + go + 16, okA);
            cpa16(d + OFF_FB,      pB + go,      16);
            cpa16(d + OFF_FB + 16, pB + go + 16, 16);
            CP_COMMIT();
            CP_WAIT1();
        } else {
            CP_WAIT0();
        }
        __syncthreads();

        const uint32_t sbase = sb + (c & 1) * STG_F;
        #pragma unroll
        for (int ks = 0; ks < 2; ks++) {
            const int kb = ks * 16;
            uint32_t ah[4][4], bh[4][2];
            #pragma unroll
            for (int mt = 0; mt < 4; mt++) {
                const uint32_t off = sbase +
                    (uint32_t)((wm * 64 + mt * 16 + aRow) * PAD + kb + aColSel) * 2;
                ldsm_x4(ah[mt], off);
            }
            #pragma unroll
            for (int nt = 0; nt < 4; nt++) {
                const uint32_t off = sbase + OFF_FB +
                    (uint32_t)((wn * 32 + nt * 8 + bRow) * PAD + kb + bColSel) * 2;
                ldsm_x2(bh[nt], off);
            }
            #pragma unroll
            for (int mt = 0; mt < 4; mt++)
                #pragma unroll
                for (int nt = 0; nt < 4; nt++)
                    mma_f16(acc[mt][nt], ah[mt], bh[nt]);
        }
        __syncthreads();
    }

    #pragma unroll
    for (int mt = 0; mt < 4; mt++) {
        const int r = row0 + wm * 64 + mt * 16 + (lane >> 2);
        #pragma unroll
        for (int nt = 0; nt < 4; nt++) {
            const int c = colb + wn * 32 + nt * 8 + (lane & 3) * 2;
            if (r < M)
                *(__half2*)(C + (size_t)r * 256 + c) =
                    __floats2half2_rn(acc[mt][nt][0] + bias[c],
                                      acc[mt][nt][1] + bias[c + 1]);
            if (r + 8 < M)
                *(__half2*)(C + (size_t)(r + 8) * 256 + c) =
                    __floats2half2_rn(acc[mt][nt][2] + bias[c],
                                      acc[mt][nt][3] + bias[c + 1]);
        }
    }
}

// ======== weight prep ========
__global__ void tsplit_w(const float* __restrict__ W,
                         bf16* __restrict__ hi, bf16* __restrict__ lo, int K)
{
    const int i = blockIdx.x * blockDim.x + threadIdx.x;
    if (i < K * 256) {
        const int k = i >> 8, n = i & 255;
        const float v = W[i];
        const bf16 h = __float2bfloat16(v);
        hi[(size_t)n * K + k] = h;
        lo[(size_t)n * K + k] = __float2bfloat16(v - __bfloat162float(h));
    }
}
__global__ void tsplit_w16(const float* __restrict__ W, __half* __restrict__ wt, int K)
{
    const int i = blockIdx.x * blockDim.x + threadIdx.x;
    if (i < K * 256) {
        const int k = i >> 8, n = i & 255;
        wt[(size_t)n * K + k] = __float2half(W[i]);
    }
}

template <int RELU>
__global__ void split_all(const float* __restrict__ in,
                          bf16* __restrict__ hi, bf16* __restrict__ lo,
                          __half* __restrict__ f16, size_t n4)
{
    const size_t i = (size_t)blockIdx.x * blockDim.x + threadIdx.x;
    if (i >= n4) return;
    float4 v = ((const float4*)in)[i];
    if (RELU) {
        v.x = fmaxf(v.x, 0.f); v.y = fmaxf(v.y, 0.f);
        v.z = fmaxf(v.z, 0.f); v.w = fmaxf(v.w, 0.f);
    }
    __nv_bfloat162 h0 = __floats2bfloat162_rn(v.x, v.y);
    __nv_bfloat162 h1 = __floats2bfloat162_rn(v.z, v.w);
    __nv_bfloat162 l0 = __floats2bfloat162_rn(v.x - __low2float(h0), v.y - __high2float(h0));
    __nv_bfloat162 l1 = __floats2bfloat162_rn(v.z - __low2float(h1), v.w - __high2float(h1));
    ((__nv_bfloat162*)hi)[2 * i]     = h0;
    ((__nv_bfloat162*)hi)[2 * i + 1] = h1;
    ((__nv_bfloat162*)lo)[2 * i]     = l0;
    ((__nv_bfloat162*)lo)[2 * i + 1] = l1;
    ((__half2*)f16)[2 * i]     = __floats2half2_rn(v.x, v.y);
    ((__half2*)f16)[2 * i + 1] = __floats2half2_rn(v.z, v.w);
}

__global__ void cvt_f16(const float* __restrict__ in, __half* __restrict__ o, size_t n4)
{
    const size_t i = (size_t)blockIdx.x * blockDim.x + threadIdx.x;
    if (i >= n4) return;
    float4 v = ((const float4*)in)[i];
    ((__half2*)o)[2 * i]     = __floats2half2_rn(v.x, v.y);
    ((__half2*)o)[2 * i + 1] = __floats2half2_rn(v.z, v.w);
}

// ================= CSR build =================
__global__ void csr_zero()
{
    const int i = blockIdx.x * blockDim.x + threadIdx.x;
    if (i < Nn) { g_deg[i] = 0; g_cursor[i] = 0; }
}
__global__ void csr_count(const int* __restrict__ ei)
{
    const int i = blockIdx.x * blockDim.x + threadIdx.x;
    if (i < Ee) atomicAdd(&g_deg[ei[Ee + i]], 1);
}
__global__ void csr_scan_local()
{
    __shared__ int s[256];
    const int tid = threadIdx.x;
    const int i = blockIdx.x * 256 + tid;
    const int v = (i < Nn) ? g_deg[i] : 0;
    s[tid] = v; __syncthreads();
    for (int off = 1; off < 256; off <<= 1) {
        const int t = (tid >= off) ? s[tid - off] : 0;
        __syncthreads();
        s[tid] += t;
        __syncthreads();
    }
    if (i < Nn) g_loc[i] = s[tid] - v;
    if (tid == 255) g_bsum[blockIdx.x] = s[255];
}
__global__ void csr_scan_bsum(int nb)
{
    __shared__ int s[256];
    const int t = threadIdx.x;
    const int v = (t < nb) ? g_bsum[t] : 0;
    s[t] = v; __syncthreads();
    for (int off = 1; off < 256; off <<= 1) {
        const int u = (t >= off) ? s[t - off] : 0;
        __syncthreads();
        s[t] += u;
        __syncthreads();
    }
    if (t < nb) g_bsum[t] = s[t] - v;
}
__global__ void csr_finalize()
{
    const int i = blockIdx.x * blockDim.x + threadIdx.x;
    if (i < Nn) g_rowptr[i] = g_loc[i] + g_bsum[i >> 8];
    if (i == 0) g_rowptr[Nn] = Ee;
}
__global__ void csr_fill(const int* __restrict__ ei)
{
    const int eid = blockIdx.x * blockDim.x + threadIdx.x;
    if (eid < Ee) {
        const int src = ei[eid];
        const int dst = ei[Ee + eid];
        const int p = atomicAdd(&g_cursor[dst], 1);
        const int pos = g_rowptr[dst] + p;
        g_adj[pos]  = eid;
        g_srcp[pos] = src;
    }
}

// ====== flash softmax + aggregate (f32x2 packed math) ======
__global__ __launch_bounds__(256) void flash_agg(
    const __half* __restrict__ q, const __half* __restrict__ k,
    const __half* __restrict__ v, const __half* __restrict__ e,
    float* __restrict__ out)
{
    const int warp = (blockIdx.x * blockDim.x + threadIdx.x) >> 5;
    const int lane = threadIdx.x & 31;
    if (warp >= Nn) return;
    const int beg = g_rowptr[warp];
    const int end = g_rowptr[warp + 1];
    if (beg == end) return;

    const int co = lane * 8;
    u64 qp[4];
    { uint4 u = *(const uint4*)(q + (size_t)warp * DD + co); cvt4p(qp, u); }

    float m = -CUDART_INF_F, d = 0.f;
    u64 acc[4] = { 0ull, 0ull, 0ull, 0ull };   // packed (0.f, 0.f)

    // prefetch edge `beg`
    int src = g_srcp[beg];
    uint4 ue = *(const uint4*)(e + (size_t)beg * DD + co);
    uint4 uk = *(const uint4*)(k + (size_t)src * DD + co);
    uint4 uv = *(const uint4*)(v + (size_t)src * DD + co);

    for (int idx = beg; idx < end; idx++) {
        const uint4 ce = ue, ck = uk, cv = uv;
        if (idx + 1 < end) {
            const int s2 = g_srcp[idx + 1];
            ue = *(const uint4*)(e + (size_t)(idx + 1) * DD + co);
            uk = *(const uint4*)(k + (size_t)s2 * DD + co);
            uv = *(const uint4*)(v + (size_t)s2 * DD + co);
        }

        u64 ep[4], kp[4], vp[4];
        cvt4p(ep, ce); cvt4p(kp, ck); cvt4p(vp, cv);

        u64 dp = 0ull;
        #pragma unroll
        for (int i = 0; i < 4; i++)
            dp = f2_fma(qp[i], f2_add(kp[i], ep[i]), dp);
        float2 dt = f2_unpack(dp);
        float dot = dt.x + dt.y;
        dot += __shfl_xor_sync(0xffffffffu, dot, 1);
        dot += __shfl_xor_sync(0xffffffffu, dot, 2);
        dot += __shfl_xor_sync(0xffffffffu, dot, 4);
        const float al = dot * 0.125f;

        const float mn = fmaxf(m, al);
        const float sc = __expf(m - mn);
        const float w  = __expf(al - mn);
        d = d * sc + w;
        const u64 sc2 = f2_pack(sc, sc);
        const u64 w2  = f2_pack(w, w);
        #pragma unroll
        for (int i = 0; i < 4; i++)
            acc[i] = f2_fma(f2_add(vp[i], ep[i]), w2, f2_mul(acc[i], sc2));
        m = mn;
    }

    const float inv = 1.f / (d + 1e-16f);
    float* op = out + (size_t)warp * DD + co;
    #pragma unroll
    for (int i = 0; i < 4; i++) {
        float2 t = f2_unpack(acc[i]);
        float2 o = *(float2*)(op + i * 2);
        o.x += t.x * inv;
        o.y += t.y * inv;
        *(float2*)(op + i * 2) = o;
    }
}

// ================= host driver =================
static void* symaddr(const void* sym)
{
    void* p = nullptr;
    cudaGetSymbolAddress(&p, sym);
    return p;
}

extern "C" void kernel_launch(void* const* d_in, const int* in_sizes, int n_in,
                              void* d_out, int out_size)
{
    const float* x  = (const float*)d_in[0];
    const int*   ei = (const int*)d_in[1];
    const float* ea = (const float*)d_in[2];
    const float* W1[5] = { (const float*)d_in[3],  (const float*)d_in[5],
                           (const float*)d_in[7],  (const float*)d_in[9],
                           (const float*)d_in[11] };
    const float* b1[5] = { (const float*)d_in[4],  (const float*)d_in[6],
                           (const float*)d_in[8],  (const float*)d_in[10],
                           (const float*)d_in[12] };
    const float* W2[5] = { (const float*)d_in[13], (const float*)d_in[15],
                           (const float*)d_in[17], (const float*)d_in[19],
                           (const float*)d_in[21] };
    const float* b2[5] = { (const float*)d_in[14], (const float*)d_in[16],
                           (const float*)d_in[18], (const float*)d_in[20],
                           (const float*)d_in[22] };

    static __half *q = nullptr, *k, *v, *e1, *e2, *eaf, *wef, *wqkv, *xf;
    static float *h;
    static bf16 *xhi, *xlo, *whi, *wlo;
    static int *adj;
    static cudaStream_t sB;
    static cudaEvent_t evRoot, evCSR, evE1, evE2;
    if (!q) {
        q  = (__half*)symaddr(g_q);  k  = (__half*)symaddr(g_k);
        v  = (__half*)symaddr(g_v);  h  = (float*)symaddr(g_h);
        e1 = (__half*)symaddr(g_e1); e2 = (__half*)symaddr(g_e2);
        eaf = (__half*)symaddr(g_eaf16); wef = (__half*)symaddr(g_wef16);
        wqkv = (__half*)symaddr(g_wqkv16); xf = (__half*)symaddr(g_xf16);
        xhi = (bf16*)symaddr(g_xhi); xlo = (bf16*)symaddr(g_xlo);
        whi = (bf16*)symaddr(g_whi); wlo = (bf16*)symaddr(g_wlo);
        adj = (int*)symaddr(g_adj);
        cudaFuncSetAttribute(gemm_bf3,
            cudaFuncAttributeMaxDynamicSharedMemorySize, GEMM_SMEM);
        cudaFuncSetAttribute(gemm_f16,
            cudaFuncAttributeMaxDynamicSharedMemorySize, GEMMF_SMEM);
        cudaStreamCreateWithFlags(&sB, cudaStreamNonBlocking);
        cudaEventCreateWithFlags(&evRoot, cudaEventDisableTiming);
        cudaEventCreateWithFlags(&evCSR,  cudaEventDisableTiming);
        cudaEventCreateWithFlags(&evE1,   cudaEventDisableTiming);
        cudaEventCreateWithFlags(&evE2,   cudaEventDisableTiming);
    }
    float* out = (float*)d_out;

    const dim3 gQKV(6, (Nn + 127) / 128);
    const dim3 gS(2, (Nn + 127) / 128);
    const dim3 gE(2, Ee / 128);
    const int  bFlash = (Nn * 32 + 255) / 256;
    const int  bSplit = (Nn * DD / 4 + 255) / 256;
    const int  NB = (Nn + 255) / 256;

    // ================= fork =================
    cudaEventRecord(evRoot, 0);
    cudaStreamWaitEvent(sB, evRoot, 0);

    // main: CSR first (consumed by sB edge GEMMs)
    csr_zero<<<NB, 256>>>();
    csr_count<<<(Ee + 255) / 256, 256>>>(ei);
    csr_scan_local<<<NB, 256>>>();
    csr_scan_bsum<<<1, 256>>>(NB);
    csr_finalize<<<NB, 256>>>();
    csr_fill<<<(Ee + 255) / 256, 256>>>(ei);
    cudaEventRecord(evCSR, 0);

    // sB: edge-side prep + GEMMs
    tsplit_w16<<<128, 256, 0, sB>>>(W1[3], wef, 128);
    tsplit_w16<<<128, 256, 0, sB>>>(W2[3], wef + 32768, 128);
    cvt_f16<<<(int)(((size_t)Ee * EDD / 4 + 255) / 256), 256, 0, sB>>>(
        ea, eaf, (size_t)Ee * EDD / 4);
    cudaStreamWaitEvent(sB, evCSR, 0);
    gemm_f16<<<gE, 256, GEMMF_SMEM, sB>>>(Ee, 128, eaf, wef, adj,
        e1, e1, e1, b1[3], b1[3], b1[3]);
    cudaEventRecord(evE1, sB);
    gemm_f16<<<gE, 256, GEMMF_SMEM, sB>>>(Ee, 128, eaf, wef + 32768, adj,
        e2, e2, e2, b2[3], b2[3], b2[3]);
    cudaEventRecord(evE2, sB);

    // main: node-side prep + layer-1 GEMMs
    for (int s = 0; s < 3; s++) {
        tsplit_w16<<<256, 256>>>(W1[s], wqkv + (size_t)s * 65536, 256);
        tsplit_w16<<<256, 256>>>(W2[s], wqkv + 196608 + (size_t)s * 65536, 256);
    }
    tsplit_w<<<256, 256>>>(W1[4], whi, wlo, 256);
    tsplit_w<<<256, 256>>>(W2[4], whi + 65536, wlo + 65536, 256);
    split_all<0><<<bSplit, 256>>>(x, xhi, xlo, xf, (size_t)Nn * DD / 4);

    gemm_f16<<<gQKV, 256, GEMMF_SMEM>>>(Nn, 256, xf, wqkv, nullptr,
        q, k, v, b1[0], b1[1], b1[2]);
    gemm_bf3<<<gS, 256, GEMM_SMEM>>>(Nn, 256, xhi, xlo, whi, wlo, h, b1[4]);

    cudaStreamWaitEvent(0, evE1, 0);
    flash_agg<<<bFlash, 256>>>(q, k, v, e1, h);
    split_all<1><<<bSplit, 256>>>(h, xhi, xlo, xf, (size_t)Nn * DD / 4);

    // main: layer 2
    gemm_f16<<<gQKV, 256, GEMMF_SMEM>>>(Nn, 256, xf, wqkv + 196608, nullptr,
        q, k, v, b2[0], b2[1], b2[2]);
    gemm_bf3<<<gS, 256, GEMM_SMEM>>>(Nn, 256, xhi, xlo,
        whi + 65536, wlo + 65536, out, b2[4]);

    cudaStreamWaitEvent(0, evE2, 0);
    flash_agg<<<bFlash, 256>>>(q, k, v, e2, out);
}

// round 13
// speedup vs baseline: 1.0697x; 1.0697x over previous
#include <cuda_runtime.h>
#include <cuda_bf16.h>
#include <cuda_fp16.h>
#include <math.h>
#include <math_constants.h>
#include <cstdint>

#define Nn   50000
#define Ee   800000
#define DD   256
#define EDD  128
#define Hh   4

typedef __nv_bfloat16 bf16;

// ================= scratch (device globals) =================
__device__ __half g_q[Nn * DD];
__device__ __half g_k[Nn * DD];
__device__ __half g_v[Nn * DD];
__device__ float  g_h[Nn * DD];
__device__ __half g_e1[(size_t)Ee * DD];
__device__ __half g_e2[(size_t)Ee * DD];
// CSR for dst-grouped edges
__device__ int g_deg[Nn];
__device__ int g_cursor[Nn];
__device__ int g_loc[Nn];
__device__ int g_bsum[256];
__device__ int g_rowptr[Nn + 1];
__device__ int g_adj[Ee];
__device__ int g_srcp[Ee];
// operands
__device__ bf16 g_xhi[Nn * DD], g_xlo[Nn * DD];
__device__ __half g_xf16[Nn * DD];
__device__ __half g_eaf16[(size_t)Ee * EDD];
__device__ bf16 g_whi[2 * 65536], g_wlo[2 * 65536];
__device__ __half g_wqkv16[2 * 768 * 256];
__device__ __half g_wef16[2 * 256 * 128];

// ================= PTX helpers =================
__device__ __forceinline__ uint32_t smem_u32(const void* p) {
    uint32_t a;
    asm("{ .reg .u64 t; cvta.to.shared.u64 t, %1; cvt.u32.u64 %0, t; }"
        : "=r"(a) : "l"(p));
    return a;
}
__device__ __forceinline__ void ldsm_x4(uint32_t* r, uint32_t a) {
    asm volatile("ldmatrix.sync.aligned.m8n8.x4.shared.b16 {%0,%1,%2,%3}, [%4];"
        : "=r"(r[0]), "=r"(r[1]), "=r"(r[2]), "=r"(r[3]) : "r"(a));
}
__device__ __forceinline__ void ldsm_x2(uint32_t* r, uint32_t a) {
    asm volatile("ldmatrix.sync.aligned.m8n8.x2.shared.b16 {%0,%1}, [%2];"
        : "=r"(r[0]), "=r"(r[1]) : "r"(a));
}
__device__ __forceinline__ void mma_bf16(float* d, const uint32_t* a, const uint32_t* b) {
    asm volatile("mma.sync.aligned.m16n8k16.row.col.f32.bf16.bf16.f32 "
        "{%0,%1,%2,%3}, {%4,%5,%6,%7}, {%8,%9}, {%0,%1,%2,%3};"
        : "+f"(d[0]), "+f"(d[1]), "+f"(d[2]), "+f"(d[3])
        : "r"(a[0]), "r"(a[1]), "r"(a[2]), "r"(a[3]), "r"(b[0]), "r"(b[1]));
}
__device__ __forceinline__ void mma_f16(float* d, const uint32_t* a, const uint32_t* b) {
    asm volatile("mma.sync.aligned.m16n8k16.row.col.f32.f16.f16.f32 "
        "{%0,%1,%2,%3}, {%4,%5,%6,%7}, {%8,%9}, {%0,%1,%2,%3};"
        : "+f"(d[0]), "+f"(d[1]), "+f"(d[2]), "+f"(d[3])
        : "r"(a[0]), "r"(a[1]), "r"(a[2]), "r"(a[3]), "r"(b[0]), "r"(b[1]));
}
__device__ __forceinline__ void cpa16(uint32_t dst, const void* src, int sz) {
    asm volatile("cp.async.cg.shared.global [%0], [%1], 16, %2;"
        :: "r"(dst), "l"(src), "r"(sz) : "memory");
}
#define CP_COMMIT() asm volatile("cp.async.commit_group;" ::: "memory")
#define CP_WAIT1()  asm volatile("cp.async.wait_group 1;" ::: "memory")
#define CP_WAIT0()  asm volatile("cp.async.wait_group 0;" ::: "memory")

// ================= bf16x3 pipelined GEMM (skip path S only) =============
#define PAD 40
#define STG_B 40960
#define OFF_AL 10240
#define OFF_BH 20480
#define OFF_BL 30720
#define GEMM_SMEM (2 * STG_B)

__global__ __launch_bounds__(256, 2) void gemm_bf3(
    int M, int K,
    const bf16* __restrict__ Ahi, const bf16* __restrict__ Alo,
    const bf16* __restrict__ Whi, const bf16* __restrict__ Wlo,
    float* __restrict__ Cf, const float* __restrict__ bias)
{
    extern __shared__ char sm[];
    const uint32_t sb = smem_u32(sm);

    const int tid  = threadIdx.x;
    const int lane = tid & 31;
    const int wid  = tid >> 5;
    const int wm   = wid >> 2;
    const int wn   = wid & 3;
    const int row0 = blockIdx.y * 128;
    const int nW0  = blockIdx.x * 128;
    const int colb = blockIdx.x * 128;

    const int lr  = tid >> 1;
    const int lcb = (tid & 1) * 16;
    const int grA  = row0 + lr;
    const int okA  = (grA < M) ? 16 : 0;
    const int arow = okA ? grA : 0;
    const size_t aoff = (size_t)arow * K + lcb;
    const size_t boff = (size_t)(nW0 + lr) * K + lcb;
    const char* pAh = (const char*)(Ahi + aoff);
    const char* pAl = (const char*)(Alo + aoff);
    const char* pBh = (const char*)(Whi + boff);
    const char* pBl = (const char*)(Wlo + boff);
    const uint32_t dstA = sb + (uint32_t)(lr * 80 + (tid & 1) * 32);

    const int nchunk = K >> 5;

    const int aRow    = lane & 15;
    const int aColSel = (lane >> 4) * 8;
    const int bRow    = lane & 7;
    const int bColSel = ((lane >> 3) & 1) * 8;

    float acc[4][4][4];
    #pragma unroll
    for (int i = 0; i < 4; i++)
        #pragma unroll
        for (int j = 0; j < 4; j++)
            #pragma unroll
            for (int t = 0; t < 4; t++) acc[i][j][t] = 0.f;

    {
        cpa16(dstA,               pAh,      okA);
        cpa16(dstA + 16,          pAh + 16, okA);
        cpa16(dstA + OFF_AL,      pAl,      okA);
        cpa16(dstA + OFF_AL + 16, pAl + 16, okA);
        cpa16(dstA + OFF_BH,      pBh,      16);
        cpa16(dstA + OFF_BH + 16, pBh + 16, 16);
        cpa16(dstA + OFF_BL,      pBl,      16);
        cpa16(dstA + OFF_BL + 16, pBl + 16, 16);
        CP_COMMIT();
    }

    for (int c = 0; c < nchunk; c++) {
        if (c + 1 < nchunk) {
            const uint32_t d = dstA + ((c + 1) & 1) * STG_B;
            const int go = (c + 1) * 64;
            cpa16(d,               pAh + go,      okA);
            cpa16(d + 16,          pAh + go + 16, okA);
            cpa16(d + OFF_AL,      pAl + go,      okA);
            cpa16(d + OFF_AL + 16, pAl + go + 16, okA);
            cpa16(d + OFF_BH,      pBh + go,      16);
            cpa16(d + OFF_BH + 16, pBh + go + 16, 16);
            cpa16(d + OFF_BL,      pBl + go,      16);
            cpa16(d + OFF_BL + 16, pBl + go + 16, 16);
            CP_COMMIT();
            CP_WAIT1();
        } else {
            CP_WAIT0();
        }
        __syncthreads();

        const uint32_t sbase = sb + (c & 1) * STG_B;
        #pragma unroll
        for (int ks = 0; ks < 2; ks++) {
            const int kb = ks * 16;
            uint32_t ah[4][4], al[4][4], bh[4][2], bl[4][2];
            #pragma unroll
            for (int mt = 0; mt < 4; mt++) {
                const uint32_t off = sbase +
                    (uint32_t)((wm * 64 + mt * 16 + aRow) * PAD + kb + aColSel) * 2;
                ldsm_x4(ah[mt], off);
                ldsm_x4(al[mt], off + OFF_AL);
            }
            #pragma unroll
            for (int nt = 0; nt < 4; nt++) {
                const uint32_t off = sbase + OFF_BH +
                    (uint32_t)((wn * 32 + nt * 8 + bRow) * PAD + kb + bColSel) * 2;
                ldsm_x2(bh[nt], off);
                ldsm_x2(bl[nt], off + (OFF_BL - OFF_BH));
            }
            #pragma unroll
            for (int mt = 0; mt < 4; mt++)
                #pragma unroll
                for (int nt = 0; nt < 4; nt++) {
                    mma_bf16(acc[mt][nt], ah[mt], bh[nt]);
                    mma_bf16(acc[mt][nt], ah[mt], bl[nt]);
                    mma_bf16(acc[mt][nt], al[mt], bh[nt]);
                }
        }
        __syncthreads();
    }

    #pragma unroll
    for (int mt = 0; mt < 4; mt++) {
        const int r = row0 + wm * 64 + mt * 16 + (lane >> 2);
        #pragma unroll
        for (int nt = 0; nt < 4; nt++) {
            const int c = colb + wn * 32 + nt * 8 + (lane & 3) * 2;
            if (r < M) {
                float2 o = make_float2(acc[mt][nt][0] + bias[c],
                                       acc[mt][nt][1] + bias[c + 1]);
                *(float2*)(Cf + (size_t)r * 256 + c) = o;
            }
            if (r + 8 < M) {
                float2 o = make_float2(acc[mt][nt][2] + bias[c],
                                       acc[mt][nt][3] + bias[c + 1]);
                *(float2*)(Cf + (size_t)(r + 8) * 256 + c) = o;
            }
        }
    }
}

// ============ single-pass fp16 GEMM, up to 3 routed fp16 outputs ============
#define STG_F 20480
#define OFF_FB 10240
#define GEMMF_SMEM (2 * STG_F)

__global__ __launch_bounds__(256, 2) void gemm_f16(
    int M, int K,
    const __half* __restrict__ A, const __half* __restrict__ W,
    const int* __restrict__ rowmap,
    __half* c0, __half* c1, __half* c2,
    const float* b0, const float* b1, const float* b2)
{
    extern __shared__ char sm[];
    const uint32_t sb = smem_u32(sm);

    const int tid  = threadIdx.x;
    const int lane = tid & 31;
    const int wid  = tid >> 5;
    const int wm   = wid >> 2;
    const int wn   = wid & 3;
    const int row0 = blockIdx.y * 128;

    __half* const outs[3]        = { c0, c1, c2 };
    const float* const biases[3] = { b0, b1, b2 };
    const int    outIdx = blockIdx.x >> 1;
    __half*      C    = outs[outIdx];
    const float* bias = biases[outIdx];
    const int    colb = (blockIdx.x & 1) * 128;
    const int    nW0  = outIdx * 256 + colb;

    const int lr  = tid >> 1;
    const int lcb = (tid & 1) * 16;
    const int grA = row0 + lr;
    const int okA = (grA < M) ? 16 : 0;
    int arow = okA ? grA : 0;
    if (rowmap) arow = rowmap[arow];
    const char* pA = (const char*)(A + (size_t)arow * K + lcb);
    const char* pB = (const char*)(W + (size_t)(nW0 + lr) * K + lcb);
    const uint32_t dstA = sb + (uint32_t)(lr * 80 + (tid & 1) * 32);

    const int nchunk = K >> 5;

    const int aRow    = lane & 15;
    const int aColSel = (lane >> 4) * 8;
    const int bRow    = lane & 7;
    const int bColSel = ((lane >> 3) & 1) * 8;

    float acc[4][4][4];
    #pragma unroll
    for (int i = 0; i < 4; i++)
        #pragma unroll
        for (int j = 0; j < 4; j++)
            #pragma unroll
            for (int t = 0; t < 4; t++) acc[i][j][t] = 0.f;

    {
        cpa16(dstA,                pA,      okA);
        cpa16(dstA + 16,           pA + 16, okA);
        cpa16(dstA + OFF_FB,       pB,      16);
        cpa16(dstA + OFF_FB + 16,  pB + 16, 16);
        CP_COMMIT();
    }

    for (int c = 0; c < nchunk; c++) {
        if (c + 1 < nchunk) {
            const uint32_t d = dstA + ((c + 1) & 1) * STG_F;
            const int go = (c + 1) * 64;
            cpa16(d,               pA + go,      okA);
            cpa16(d + 16,          pA + go + 16, okA);
            cpa16(d + OFF_FB,      pB + go,      16);
            cpa16(d + OFF_FB + 16, pB + go + 16, 16);
            CP_COMMIT();
            CP_WAIT1();
        } else {
            CP_WAIT0();
        }
        __syncthreads();

        const uint32_t sbase = sb + (c & 1) * STG_F;
        #pragma unroll
        for (int ks = 0; ks < 2; ks++) {
            const int kb = ks * 16;
            uint32_t ah[4][4], bh[4][2];
            #pragma unroll
            for (int mt = 0; mt < 4; mt++) {
                const uint32_t off = sbase +
                    (uint32_t)((wm * 64 + mt * 16 + aRow) * PAD + kb + aColSel) * 2;
                ldsm_x4(ah[mt], off);
            }
            #pragma unroll
            for (int nt = 0; nt < 4; nt++) {
                const uint32_t off = sbase + OFF_FB +
                    (uint32_t)((wn * 32 + nt * 8 + bRow) * PAD + kb + bColSel) * 2;
                ldsm_x2(bh[nt], off);
            }
            #pragma unroll
            for (int mt = 0; mt < 4; mt++)
                #pragma unroll
                for (int nt = 0; nt < 4; nt++)
                    mma_f16(acc[mt][nt], ah[mt], bh[nt]);
        }
        __syncthreads();
    }

    #pragma unroll
    for (int mt = 0; mt < 4; mt++) {
        const int r = row0 + wm * 64 + mt * 16 + (lane >> 2);
        #pragma unroll
        for (int nt = 0; nt < 4; nt++) {
            const int c = colb + wn * 32 + nt * 8 + (lane & 3) * 2;
            if (r < M)
                *(__half2*)(C + (size_t)r * 256 + c) =
                    __floats2half2_rn(acc[mt][nt][0] + bias[c],
                                      acc[mt][nt][1] + bias[c + 1]);
            if (r + 8 < M)
                *(__half2*)(C + (size_t)(r + 8) * 256 + c) =
                    __floats2half2_rn(acc[mt][nt][2] + bias[c],
                                      acc[mt][nt][3] + bias[c + 1]);
        }
    }
}

// ======== weight prep ========
__global__ void tsplit_w(const float* __restrict__ W,
                         bf16* __restrict__ hi, bf16* __restrict__ lo, int K)
{
    const int i = blockIdx.x * blockDim.x + threadIdx.x;
    if (i < K * 256) {
        const int k = i >> 8, n = i & 255;
        const float v = W[i];
        const bf16 h = __float2bfloat16(v);
        hi[(size_t)n * K + k] = h;
        lo[(size_t)n * K + k] = __float2bfloat16(v - __bfloat162float(h));
    }
}
__global__ void tsplit_w16(const float* __restrict__ W, __half* __restrict__ wt, int K)
{
    const int i = blockIdx.x * blockDim.x + threadIdx.x;
    if (i < K * 256) {
        const int k = i >> 8, n = i & 255;
        wt[(size_t)n * K + k] = __float2half(W[i]);
    }
}

template <int RELU>
__global__ void split_all(const float* __restrict__ in,
                          bf16* __restrict__ hi, bf16* __restrict__ lo,
                          __half* __restrict__ f16, size_t n4)
{
    const size_t i = (size_t)blockIdx.x * blockDim.x + threadIdx.x;
    if (i >= n4) return;
    float4 v = ((const float4*)in)[i];
    if (RELU) {
        v.x = fmaxf(v.x, 0.f); v.y = fmaxf(v.y, 0.f);
        v.z = fmaxf(v.z, 0.f); v.w = fmaxf(v.w, 0.f);
    }
    __nv_bfloat162 h0 = __floats2bfloat162_rn(v.x, v.y);
    __nv_bfloat162 h1 = __floats2bfloat162_rn(v.z, v.w);
    __nv_bfloat162 l0 = __floats2bfloat162_rn(v.x - __low2float(h0), v.y - __high2float(h0));
    __nv_bfloat162 l1 = __floats2bfloat162_rn(v.z - __low2float(h1), v.w - __high2float(h1));
    ((__nv_bfloat162*)hi)[2 * i]     = h0;
    ((__nv_bfloat162*)hi)[2 * i + 1] = h1;
    ((__nv_bfloat162*)lo)[2 * i]     = l0;
    ((__nv_bfloat162*)lo)[2 * i + 1] = l1;
    ((__half2*)f16)[2 * i]     = __floats2half2_rn(v.x, v.y);
    ((__half2*)f16)[2 * i + 1] = __floats2half2_rn(v.z, v.w);
}

__global__ void cvt_f16(const float* __restrict__ in, __half* __restrict__ o, size_t n4)
{
    const size_t i = (size_t)blockIdx.x * blockDim.x + threadIdx.x;
    if (i >= n4) return;
    float4 v = ((const float4*)in)[i];
    ((__half2*)o)[2 * i]     = __floats2half2_rn(v.x, v.y);
    ((__half2*)o)[2 * i + 1] = __floats2half2_rn(v.z, v.w);
}

// ================= CSR build =================
__global__ void csr_zero()
{
    const int i = blockIdx.x * blockDim.x + threadIdx.x;
    if (i < Nn) { g_deg[i] = 0; g_cursor[i] = 0; }
}
__global__ void csr_count(const int* __restrict__ ei)
{
    const int i = blockIdx.x * blockDim.x + threadIdx.x;
    if (i < Ee) atomicAdd(&g_deg[ei[Ee + i]], 1);
}
__global__ void csr_scan_local()
{
    __shared__ int s[256];
    const int tid = threadIdx.x;
    const int i = blockIdx.x * 256 + tid;
    const int v = (i < Nn) ? g_deg[i] : 0;
    s[tid] = v; __syncthreads();
    for (int off = 1; off < 256; off <<= 1) {
        const int t = (tid >= off) ? s[tid - off] : 0;
        __syncthreads();
        s[tid] += t;
        __syncthreads();
    }
    if (i < Nn) g_loc[i] = s[tid] - v;
    if (tid == 255) g_bsum[blockIdx.x] = s[255];
}
__global__ void csr_scan_bsum(int nb)
{
    __shared__ int s[256];
    const int t = threadIdx.x;
    const int v = (t < nb) ? g_bsum[t] : 0;
    s[t] = v; __syncthreads();
    for (int off = 1; off < 256; off <<= 1) {
        const int u = (t >= off) ? s[t - off] : 0;
        __syncthreads();
        s[t] += u;
        __syncthreads();
    }
    if (t < nb) g_bsum[t] = s[t] - v;
}
__global__ void csr_finalize()
{
    const int i = blockIdx.x * blockDim.x + threadIdx.x;
    if (i < Nn) g_rowptr[i] = g_loc[i] + g_bsum[i >> 8];
    if (i == 0) g_rowptr[Nn] = Ee;
}
__global__ void csr_fill(const int* __restrict__ ei)
{
    const int eid = blockIdx.x * blockDim.x + threadIdx.x;
    if (eid < Ee) {
        const int src = ei[eid];
        const int dst = ei[Ee + eid];
        const int p = atomicAdd(&g_cursor[dst], 1);
        const int pos = g_rowptr[dst] + p;
        g_adj[pos]  = eid;
        g_srcp[pos] = src;
    }
}

// ====== flash softmax + aggregate (half2 adds, fp32 dot/accum) ======
__global__ __launch_bounds__(256) void flash_agg(
    const __half* __restrict__ q, const __half* __restrict__ k,
    const __half* __restrict__ v, const __half* __restrict__ e,
    float* __restrict__ out)
{
    const int warp = (blockIdx.x * blockDim.x + threadIdx.x) >> 5;
    const int lane = threadIdx.x & 31;
    if (warp >= Nn) return;
    const int beg = g_rowptr[warp];
    const int end = g_rowptr[warp + 1];
    if (beg == end) return;

    const int co = lane * 8;
    float qf[8];
    {
        uint4 u = *(const uint4*)(q + (size_t)warp * DD + co);
        const __half2* h = (const __half2*)&u;
        #pragma unroll
        for (int i = 0; i < 4; i++) {
            float2 t = __half22float2(h[i]);
            qf[2 * i] = t.x; qf[2 * i + 1] = t.y;
        }
    }

    float m = -CUDART_INF_F, d = 0.f;
    float a[8];
    #pragma unroll
    for (int i = 0; i < 8; i++) a[i] = 0.f;

    // prefetch edge `beg`
    int src = g_srcp[beg];
    uint4 ue = *(const uint4*)(e + (size_t)beg * DD + co);
    uint4 uk = *(const uint4*)(k + (size_t)src * DD + co);
    uint4 uv = *(const uint4*)(v + (size_t)src * DD + co);

    for (int idx = beg; idx < end; idx++) {
        const uint4 ce = ue, ck = uk, cv = uv;
        if (idx + 1 < end) {
            const int s2 = g_srcp[idx + 1];
            ue = *(const uint4*)(e + (size_t)(idx + 1) * DD + co);
            uk = *(const uint4*)(k + (size_t)s2 * DD + co);
            uv = *(const uint4*)(v + (size_t)s2 * DD + co);
        }

        const __half2* eh = (const __half2*)&ce;
        const __half2* kh = (const __half2*)&ck;
        const __half2* vh = (const __half2*)&cv;

        // ke = k + e (half2), dot in fp32
        float2 kef[4];
        #pragma unroll
        for (int i = 0; i < 4; i++)
            kef[i] = __half22float2(__hadd2(kh[i], eh[i]));
        float dot = 0.f;
        #pragma unroll
        for (int i = 0; i < 4; i++) {
            dot = fmaf(qf[2 * i],     kef[i].x, dot);
            dot = fmaf(qf[2 * i + 1], kef[i].y, dot);
        }
        dot += __shfl_xor_sync(0xffffffffu, dot, 1);
        dot += __shfl_xor_sync(0xffffffffu, dot, 2);
        dot += __shfl_xor_sync(0xffffffffu, dot, 4);
        const float al = dot * 0.125f;

        const float mn = fmaxf(m, al);
        const float sc = __expf(m - mn);
        const float w  = __expf(al - mn);
        d = d * sc + w;
        #pragma unroll
        for (int i = 0; i < 4; i++) {
            float2 vef = __half22float2(__hadd2(vh[i], eh[i]));
            a[2 * i]     = fmaf(vef.x, w, a[2 * i] * sc);
            a[2 * i + 1] = fmaf(vef.y, w, a[2 * i + 1] * sc);
        }
        m = mn;
    }

    const float inv = 1.f / (d + 1e-16f);
    float* op = out + (size_t)warp * DD + co;
    float4 o0 = *(float4*)op, o1 = *(float4*)(op + 4);
    o0.x += a[0] * inv; o0.y += a[1] * inv;
    o0.z += a[2] * inv; o0.w += a[3] * inv;
    o1.x += a[4] * inv; o1.y += a[5] * inv;
    o1.z += a[6] * inv; o1.w += a[7] * inv;
    *(float4*)op       = o0;
    *(float4*)(op + 4) = o1;
}

// ================= host driver =================
static void* symaddr(const void* sym)
{
    void* p = nullptr;
    cudaGetSymbolAddress(&p, sym);
    return p;
}

extern "C" void kernel_launch(void* const* d_in, const int* in_sizes, int n_in,
                              void* d_out, int out_size)
{
    const float* x  = (const float*)d_in[0];
    const int*   ei = (const int*)d_in[1];
    const float* ea = (const float*)d_in[2];
    const float* W1[5] = { (const float*)d_in[3],  (const float*)d_in[5],
                           (const float*)d_in[7],  (const float*)d_in[9],
                           (const float*)d_in[11] };
    const float* b1[5] = { (const float*)d_in[4],  (const float*)d_in[6],
                           (const float*)d_in[8],  (const float*)d_in[10],
                           (const float*)d_in[12] };
    const float* W2[5] = { (const float*)d_in[13], (const float*)d_in[15],
                           (const float*)d_in[17], (const float*)d_in[19],
                           (const float*)d_in[21] };
    const float* b2[5] = { (const float*)d_in[14], (const float*)d_in[16],
                           (const float*)d_in[18], (const float*)d_in[20],
                           (const float*)d_in[22] };

    static __half *q = nullptr, *k, *v, *e1, *e2, *eaf, *wef, *wqkv, *xf;
    static float *h;
    static bf16 *xhi, *xlo, *whi, *wlo;
    static int *adj;
    static cudaStream_t sB;
    static cudaEvent_t evRoot, evE1, evE2;
    if (!q) {
        q  = (__half*)symaddr(g_q);  k  = (__half*)symaddr(g_k);
        v  = (__half*)symaddr(g_v);  h  = (float*)symaddr(g_h);
        e1 = (__half*)symaddr(g_e1); e2 = (__half*)symaddr(g_e2);
        eaf = (__half*)symaddr(g_eaf16); wef = (__half*)symaddr(g_wef16);
        wqkv = (__half*)symaddr(g_wqkv16); xf = (__half*)symaddr(g_xf16);
        xhi = (bf16*)symaddr(g_xhi); xlo = (bf16*)symaddr(g_xlo);
        whi = (bf16*)symaddr(g_whi); wlo = (bf16*)symaddr(g_wlo);
        adj = (int*)symaddr(g_adj);
        cudaFuncSetAttribute(gemm_bf3,
            cudaFuncAttributeMaxDynamicSharedMemorySize, GEMM_SMEM);
        cudaFuncSetAttribute(gemm_f16,
            cudaFuncAttributeMaxDynamicSharedMemorySize, GEMMF_SMEM);
        cudaStreamCreateWithFlags(&sB, cudaStreamNonBlocking);
        cudaEventCreateWithFlags(&evRoot, cudaEventDisableTiming);
        cudaEventCreateWithFlags(&evE1,   cudaEventDisableTiming);
        cudaEventCreateWithFlags(&evE2,   cudaEventDisableTiming);
    }
    float* out = (float*)d_out;

    const dim3 gQKV(6, (Nn + 127) / 128);
    const dim3 gS(2, (Nn + 127) / 128);
    const dim3 gE(2, Ee / 128);
    const int  bFlash = (Nn * 32 + 255) / 256;
    const int  bSplit = (Nn * DD / 4 + 255) / 256;
    const int  NB = (Nn + 255) / 256;

    // ================= fork =================
    cudaEventRecord(evRoot, 0);
    cudaStreamWaitEvent(sB, evRoot, 0);

    // sB: edge-side prep + CSR + edge GEMMs (R11 schedule)
    tsplit_w16<<<128, 256, 0, sB>>>(W1[3], wef, 128);
    tsplit_w16<<<128, 256, 0, sB>>>(W2[3], wef + 32768, 128);
    csr_zero<<<NB, 256, 0, sB>>>();
    csr_count<<<(Ee + 255) / 256, 256, 0, sB>>>(ei);
    csr_scan_local<<<NB, 256, 0, sB>>>();
    csr_scan_bsum<<<1, 256, 0, sB>>>(NB);
    csr_finalize<<<NB, 256, 0, sB>>>();
    csr_fill<<<(Ee + 255) / 256, 256, 0, sB>>>(ei);
    cvt_f16<<<(int)(((size_t)Ee * EDD / 4 + 255) / 256), 256, 0, sB>>>(
        ea, eaf, (size_t)Ee * EDD / 4);
    gemm_f16<<<gE, 256, GEMMF_SMEM, sB>>>(Ee, 128, eaf, wef, adj,
        e1, e1, e1, b1[3], b1[3], b1[3]);
    cudaEventRecord(evE1, sB);
    gemm_f16<<<gE, 256, GEMMF_SMEM, sB>>>(Ee, 128, eaf, wef + 32768, adj,
        e2, e2, e2, b2[3], b2[3], b2[3]);
    cudaEventRecord(evE2, sB);

    // main: node-side prep + layer-1 GEMMs
    for (int s = 0; s < 3; s++) {
        tsplit_w16<<<256, 256>>>(W1[s], wqkv + (size_t)s * 65536, 256);
        tsplit_w16<<<256, 256>>>(W2[s], wqkv + 196608 + (size_t)s * 65536, 256);
    }
    tsplit_w<<<256, 256>>>(W1[4], whi, wlo, 256);
    tsplit_w<<<256, 256>>>(W2[4], whi + 65536, wlo + 65536, 256);
    split_all<0><<<bSplit, 256>>>(x, xhi, xlo, xf, (size_t)Nn * DD / 4);

    gemm_f16<<<gQKV, 256, GEMMF_SMEM>>>(Nn, 256, xf, wqkv, nullptr,
        q, k, v, b1[0], b1[1], b1[2]);
    gemm_bf3<<<gS, 256, GEMM_SMEM>>>(Nn, 256, xhi, xlo, whi, wlo, h, b1[4]);

    cudaStreamWaitEvent(0, evE1, 0);
    flash_agg<<<bFlash, 256>>>(q, k, v, e1, h);
    split_all<1><<<bSplit, 256>>>(h, xhi, xlo, xf, (size_t)Nn * DD / 4);

    // main: layer 2
    gemm_f16<<<gQKV, 256, GEMMF_SMEM>>>(Nn, 256, xf, wqkv + 196608, nullptr,
        q, k, v, b2[0], b2[1], b2[2]);
    gemm_bf3<<<gS, 256, GEMM_SMEM>>>(Nn, 256, xhi, xlo,
        whi + 65536, wlo + 65536, out, b2[4]);

    cudaStreamWaitEvent(0, evE2, 0);
    flash_agg<<<bFlash, 256>>>(q, k, v, e2, out);
}

// round 14
// speedup vs baseline: 1.1309x; 1.0572x over previous
#include <cuda_runtime.h>
#include <cuda_fp16.h>
#include <math.h>
#include <math_constants.h>
#include <cstdint>

#define Nn   50000
#define Ee   800000
#define DD   256
#define EDD  128
#define Hh   4

// ================= scratch (device globals) =================
__device__ __half g_q[Nn * DD];
__device__ __half g_k[Nn * DD];
__device__ __half g_v[Nn * DD];
__device__ float  g_h[Nn * DD];
__device__ __half g_e1[(size_t)Ee * DD];
__device__ __half g_e2[(size_t)Ee * DD];
// CSR for dst-grouped edges
__device__ int g_deg[Nn];
__device__ int g_cursor[Nn];
__device__ int g_loc[Nn];
__device__ int g_bsum[256];
__device__ int g_rowptr[Nn + 1];
__device__ int g_adj[Ee];
__device__ int g_srcp[Ee];
// operands
__device__ __half g_xf16[Nn * DD];
__device__ __half g_eaf16[(size_t)Ee * EDD];
__device__ __half g_wqkvs16[2 * 1024 * 256];   // fused Q,K,V,S fp16 K-major
__device__ __half g_wef16[2 * 256 * 128];      // edge weights fp16 K-major

// ================= PTX helpers =================
__device__ __forceinline__ uint32_t smem_u32(const void* p) {
    uint32_t a;
    asm("{ .reg .u64 t; cvta.to.shared.u64 t, %1; cvt.u32.u64 %0, t; }"
        : "=r"(a) : "l"(p));
    return a;
}
__device__ __forceinline__ void ldsm_x4(uint32_t* r, uint32_t a) {
    asm volatile("ldmatrix.sync.aligned.m8n8.x4.shared.b16 {%0,%1,%2,%3}, [%4];"
        : "=r"(r[0]), "=r"(r[1]), "=r"(r[2]), "=r"(r[3]) : "r"(a));
}
__device__ __forceinline__ void ldsm_x2(uint32_t* r, uint32_t a) {
    asm volatile("ldmatrix.sync.aligned.m8n8.x2.shared.b16 {%0,%1}, [%2];"
        : "=r"(r[0]), "=r"(r[1]) : "r"(a));
}
__device__ __forceinline__ void mma_f16(float* d, const uint32_t* a, const uint32_t* b) {
    asm volatile("mma.sync.aligned.m16n8k16.row.col.f32.f16.f16.f32 "
        "{%0,%1,%2,%3}, {%4,%5,%6,%7}, {%8,%9}, {%0,%1,%2,%3};"
        : "+f"(d[0]), "+f"(d[1]), "+f"(d[2]), "+f"(d[3])
        : "r"(a[0]), "r"(a[1]), "r"(a[2]), "r"(a[3]), "r"(b[0]), "r"(b[1]));
}
__device__ __forceinline__ void cpa16(uint32_t dst, const void* src, int sz) {
    asm volatile("cp.async.cg.shared.global [%0], [%1], 16, %2;"
        :: "r"(dst), "l"(src), "r"(sz) : "memory");
}
#define CP_COMMIT() asm volatile("cp.async.commit_group;" ::: "memory")
#define CP_WAIT1()  asm volatile("cp.async.wait_group 1;" ::: "memory")
#define CP_WAIT0()  asm volatile("cp.async.wait_group 0;" ::: "memory")

// ============ fp16 GEMM, up to 4 routed outputs (0-2 fp16, 3 fp32) ============
// grid.x = 2 * numOutputs; output i uses weight rows [i*256, i*256+256) of W
#define PAD 40
#define STG_F 20480
#define OFF_FB 10240
#define GEMMF_SMEM (2 * STG_F)

__global__ __launch_bounds__(256, 2) void gemm_multi(
    int M, int K,
    const __half* __restrict__ A, const __half* __restrict__ W,
    const int* __restrict__ rowmap,
    __half* c0, __half* c1, __half* c2, float* c3,
    const float* b0, const float* b1, const float* b2, const float* b3)
{
    extern __shared__ char sm[];
    const uint32_t sb = smem_u32(sm);

    const int tid  = threadIdx.x;
    const int lane = tid & 31;
    const int wid  = tid >> 5;
    const int wm   = wid >> 2;
    const int wn   = wid & 3;
    const int row0 = blockIdx.y * 128;

    __half* const houts[3]       = { c0, c1, c2 };
    const float* const biases[4] = { b0, b1, b2, b3 };
    const int    outIdx = blockIdx.x >> 1;
    const float* bias   = biases[outIdx];
    const int    colb   = (blockIdx.x & 1) * 128;
    const int    nW0    = outIdx * 256 + colb;

    const int lr  = tid >> 1;
    const int lcb = (tid & 1) * 16;
    const int grA = row0 + lr;
    const int okA = (grA < M) ? 16 : 0;
    int arow = okA ? grA : 0;
    if (rowmap) arow = rowmap[arow];
    const char* pA = (const char*)(A + (size_t)arow * K + lcb);
    const char* pB = (const char*)(W + (size_t)(nW0 + lr) * K + lcb);
    const uint32_t dstA = sb + (uint32_t)(lr * 80 + (tid & 1) * 32);

    const int nchunk = K >> 5;

    const int aRow    = lane & 15;
    const int aColSel = (lane >> 4) * 8;
    const int bRow    = lane & 7;
    const int bColSel = ((lane >> 3) & 1) * 8;

    float acc[4][4][4];
    #pragma unroll
    for (int i = 0; i < 4; i++)
        #pragma unroll
        for (int j = 0; j < 4; j++)
            #pragma unroll
            for (int t = 0; t < 4; t++) acc[i][j][t] = 0.f;

    {
        cpa16(dstA,                pA,      okA);
        cpa16(dstA + 16,           pA + 16, okA);
        cpa16(dstA + OFF_FB,       pB,      16);
        cpa16(dstA + OFF_FB + 16,  pB + 16, 16);
        CP_COMMIT();
    }

    for (int c = 0; c < nchunk; c++) {
        if (c + 1 < nchunk) {
            const uint32_t d = dstA + ((c + 1) & 1) * STG_F;
            const int go = (c + 1) * 64;
            cpa16(d,               pA + go,      okA);
            cpa16(d + 16,          pA + go + 16, okA);
            cpa16(d + OFF_FB,      pB + go,      16);
            cpa16(d + OFF_FB + 16, pB + go + 16, 16);
            CP_COMMIT();
            CP_WAIT1();
        } else {
            CP_WAIT0();
        }
        __syncthreads();

        const uint32_t sbase = sb + (c & 1) * STG_F;
        #pragma unroll
        for (int ks = 0; ks < 2; ks++) {
            const int kb = ks * 16;
            uint32_t ah[4][4], bh[4][2];
            #pragma unroll
            for (int mt = 0; mt < 4; mt++) {
                const uint32_t off = sbase +
                    (uint32_t)((wm * 64 + mt * 16 + aRow) * PAD + kb + aColSel) * 2;
                ldsm_x4(ah[mt], off);
            }
            #pragma unroll
            for (int nt = 0; nt < 4; nt++) {
                const uint32_t off = sbase + OFF_FB +
                    (uint32_t)((wn * 32 + nt * 8 + bRow) * PAD + kb + bColSel) * 2;
                ldsm_x2(bh[nt], off);
            }
            #pragma unroll
            for (int mt = 0; mt < 4; mt++)
                #pragma unroll
                for (int nt = 0; nt < 4; nt++)
                    mma_f16(acc[mt][nt], ah[mt], bh[nt]);
        }
        __syncthreads();
    }

    if (outIdx < 3) {
        __half* C = houts[outIdx];
        #pragma unroll
        for (int mt = 0; mt < 4; mt++) {
            const int r = row0 + wm * 64 + mt * 16 + (lane >> 2);
            #pragma unroll
            for (int nt = 0; nt < 4; nt++) {
                const int c = colb + wn * 32 + nt * 8 + (lane & 3) * 2;
                if (r < M)
                    *(__half2*)(C + (size_t)r * 256 + c) =
                        __floats2half2_rn(acc[mt][nt][0] + bias[c],
                                          acc[mt][nt][1] + bias[c + 1]);
                if (r + 8 < M)
                    *(__half2*)(C + (size_t)(r + 8) * 256 + c) =
                        __floats2half2_rn(acc[mt][nt][2] + bias[c],
                                          acc[mt][nt][3] + bias[c + 1]);
            }
        }
    } else {
        #pragma unroll
        for (int mt = 0; mt < 4; mt++) {
            const int r = row0 + wm * 64 + mt * 16 + (lane >> 2);
            #pragma unroll
            for (int nt = 0; nt < 4; nt++) {
                const int c = colb + wn * 32 + nt * 8 + (lane & 3) * 2;
                if (r < M) {
                    float2 o = make_float2(acc[mt][nt][0] + bias[c],
                                           acc[mt][nt][1] + bias[c + 1]);
                    *(float2*)(c3 + (size_t)r * 256 + c) = o;
                }
                if (r + 8 < M) {
                    float2 o = make_float2(acc[mt][nt][2] + bias[c],
                                           acc[mt][nt][3] + bias[c + 1]);
                    *(float2*)(c3 + (size_t)(r + 8) * 256 + c) = o;
                }
            }
        }
    }
}

// ======== weight prep: K-major fp16 transpose ========
__global__ void tsplit_w16(const float* __restrict__ W, __half* __restrict__ wt, int K)
{
    const int i = blockIdx.x * blockDim.x + threadIdx.x;
    if (i < K * 256) {
        const int k = i >> 8, n = i & 255;
        wt[(size_t)n * K + k] = __float2half(W[i]);
    }
}

// fp32 -> fp16, optional relu
template <int RELU>
__global__ void cvt_f16(const float* __restrict__ in, __half* __restrict__ o, size_t n4)
{
    const size_t i = (size_t)blockIdx.x * blockDim.x + threadIdx.x;
    if (i >= n4) return;
    float4 v = ((const float4*)in)[i];
    if (RELU) {
        v.x = fmaxf(v.x, 0.f); v.y = fmaxf(v.y, 0.f);
        v.z = fmaxf(v.z, 0.f); v.w = fmaxf(v.w, 0.f);
    }
    ((__half2*)o)[2 * i]     = __floats2half2_rn(v.x, v.y);
    ((__half2*)o)[2 * i + 1] = __floats2half2_rn(v.z, v.w);
}

// ================= CSR build =================
__global__ void csr_zero()
{
    const int i = blockIdx.x * blockDim.x + threadIdx.x;
    if (i < Nn) { g_deg[i] = 0; g_cursor[i] = 0; }
}
__global__ void csr_count(const int* __restrict__ ei)
{
    const int i = blockIdx.x * blockDim.x + threadIdx.x;
    if (i < Ee) atomicAdd(&g_deg[ei[Ee + i]], 1);
}
__global__ void csr_scan_local()
{
    __shared__ int s[256];
    const int tid = threadIdx.x;
    const int i = blockIdx.x * 256 + tid;
    const int v = (i < Nn) ? g_deg[i] : 0;
    s[tid] = v; __syncthreads();
    for (int off = 1; off < 256; off <<= 1) {
        const int t = (tid >= off) ? s[tid - off] : 0;
        __syncthreads();
        s[tid] += t;
        __syncthreads();
    }
    if (i < Nn) g_loc[i] = s[tid] - v;
    if (tid == 255) g_bsum[blockIdx.x] = s[255];
}
__global__ void csr_scan_bsum(int nb)
{
    __shared__ int s[256];
    const int t = threadIdx.x;
    const int v = (t < nb) ? g_bsum[t] : 0;
    s[t] = v; __syncthreads();
    for (int off = 1; off < 256; off <<= 1) {
        const int u = (t >= off) ? s[t - off] : 0;
        __syncthreads();
        s[t] += u;
        __syncthreads();
    }
    if (t < nb) g_bsum[t] = s[t] - v;
}
__global__ void csr_finalize()
{
    const int i = blockIdx.x * blockDim.x + threadIdx.x;
    if (i < Nn) g_rowptr[i] = g_loc[i] + g_bsum[i >> 8];
    if (i == 0) g_rowptr[Nn] = Ee;
}
__global__ void csr_fill(const int* __restrict__ ei)
{
    const int eid = blockIdx.x * blockDim.x + threadIdx.x;
    if (eid < Ee) {
        const int src = ei[eid];
        const int dst = ei[Ee + eid];
        const int p = atomicAdd(&g_cursor[dst], 1);
        const int pos = g_rowptr[dst] + p;
        g_adj[pos]  = eid;
        g_srcp[pos] = src;
    }
}

// ====== flash softmax + aggregate (unchanged from R13) ======
__global__ __launch_bounds__(256) void flash_agg(
    const __half* __restrict__ q, const __half* __restrict__ k,
    const __half* __restrict__ v, const __half* __restrict__ e,
    float* __restrict__ out)
{
    const int warp = (blockIdx.x * blockDim.x + threadIdx.x) >> 5;
    const int lane = threadIdx.x & 31;
    if (warp >= Nn) return;
    const int beg = g_rowptr[warp];
    const int end = g_rowptr[warp + 1];
    if (beg == end) return;

    const int co = lane * 8;
    float qf[8];
    {
        uint4 u = *(const uint4*)(q + (size_t)warp * DD + co);
        const __half2* h = (const __half2*)&u;
        #pragma unroll
        for (int i = 0; i < 4; i++) {
            float2 t = __half22float2(h[i]);
            qf[2 * i] = t.x; qf[2 * i + 1] = t.y;
        }
    }

    float m = -CUDART_INF_F, d = 0.f;
    float a[8];
    #pragma unroll
    for (int i = 0; i < 8; i++) a[i] = 0.f;

    int src = g_srcp[beg];
    uint4 ue = *(const uint4*)(e + (size_t)beg * DD + co);
    uint4 uk = *(const uint4*)(k + (size_t)src * DD + co);
    uint4 uv = *(const uint4*)(v + (size_t)src * DD + co);

    for (int idx = beg; idx < end; idx++) {
        const uint4 ce = ue, ck = uk, cv = uv;
        if (idx + 1 < end) {
            const int s2 = g_srcp[idx + 1];
            ue = *(const uint4*)(e + (size_t)(idx + 1) * DD + co);
            uk = *(const uint4*)(k + (size_t)s2 * DD + co);
            uv = *(const uint4*)(v + (size_t)s2 * DD + co);
        }

        const __half2* eh = (const __half2*)&ce;
        const __half2* kh = (const __half2*)&ck;
        const __half2* vh = (const __half2*)&cv;

        float2 kef[4];
        #pragma unroll
        for (int i = 0; i < 4; i++)
            kef[i] = __half22float2(__hadd2(kh[i], eh[i]));
        float dot = 0.f;
        #pragma unroll
        for (int i = 0; i < 4; i++) {
            dot = fmaf(qf[2 * i],     kef[i].x, dot);
            dot = fmaf(qf[2 * i + 1], kef[i].y, dot);
        }
        dot += __shfl_xor_sync(0xffffffffu, dot, 1);
        dot += __shfl_xor_sync(0xffffffffu, dot, 2);
        dot += __shfl_xor_sync(0xffffffffu, dot, 4);
        const float al = dot * 0.125f;

        const float mn = fmaxf(m, al);
        const float sc = __expf(m - mn);
        const float w  = __expf(al - mn);
        d = d * sc + w;
        #pragma unroll
        for (int i = 0; i < 4; i++) {
            float2 vef = __half22float2(__hadd2(vh[i], eh[i]));
            a[2 * i]     = fmaf(vef.x, w, a[2 * i] * sc);
            a[2 * i + 1] = fmaf(vef.y, w, a[2 * i + 1] * sc);
        }
        m = mn;
    }

    const float inv = 1.f / (d + 1e-16f);
    float* op = out + (size_t)warp * DD + co;
    float4 o0 = *(float4*)op, o1 = *(float4*)(op + 4);
    o0.x += a[0] * inv; o0.y += a[1] * inv;
    o0.z += a[2] * inv; o0.w += a[3] * inv;
    o1.x += a[4] * inv; o1.y += a[5] * inv;
    o1.z += a[6] * inv; o1.w += a[7] * inv;
    *(float4*)op       = o0;
    *(float4*)(op + 4) = o1;
}

// ================= host driver =================
static void* symaddr(const void* sym)
{
    void* p = nullptr;
    cudaGetSymbolAddress(&p, sym);
    return p;
}

extern "C" void kernel_launch(void* const* d_in, const int* in_sizes, int n_in,
                              void* d_out, int out_size)
{
    const float* x  = (const float*)d_in[0];
    const int*   ei = (const int*)d_in[1];
    const float* ea = (const float*)d_in[2];
    const float* W1[5] = { (const float*)d_in[3],  (const float*)d_in[5],
                           (const float*)d_in[7],  (const float*)d_in[9],
                           (const float*)d_in[11] };
    const float* b1[5] = { (const float*)d_in[4],  (const float*)d_in[6],
                           (const float*)d_in[8],  (const float*)d_in[10],
                           (const float*)d_in[12] };
    const float* W2[5] = { (const float*)d_in[13], (const float*)d_in[15],
                           (const float*)d_in[17], (const float*)d_in[19],
                           (const float*)d_in[21] };
    const float* b2[5] = { (const float*)d_in[14], (const float*)d_in[16],
                           (const float*)d_in[18], (const float*)d_in[20],
                           (const float*)d_in[22] };

    static __half *q = nullptr, *k, *v, *e1, *e2, *eaf, *wef, *wqkvs, *xf;
    static float *h;
    static int *adj;
    static cudaStream_t sB;
    static cudaEvent_t evRoot, evE1, evE2;
    if (!q) {
        q  = (__half*)symaddr(g_q);  k  = (__half*)symaddr(g_k);
        v  = (__half*)symaddr(g_v);  h  = (float*)symaddr(g_h);
        e1 = (__half*)symaddr(g_e1); e2 = (__half*)symaddr(g_e2);
        eaf = (__half*)symaddr(g_eaf16); wef = (__half*)symaddr(g_wef16);
        wqkvs = (__half*)symaddr(g_wqkvs16); xf = (__half*)symaddr(g_xf16);
        adj = (int*)symaddr(g_adj);
        cudaFuncSetAttribute(gemm_multi,
            cudaFuncAttributeMaxDynamicSharedMemorySize, GEMMF_SMEM);
        cudaStreamCreateWithFlags(&sB, cudaStreamNonBlocking);
        cudaEventCreateWithFlags(&evRoot, cudaEventDisableTiming);
        cudaEventCreateWithFlags(&evE1,   cudaEventDisableTiming);
        cudaEventCreateWithFlags(&evE2,   cudaEventDisableTiming);
    }
    float* out = (float*)d_out;

    const dim3 gQKVS(8, (Nn + 127) / 128);      // 4 outputs x 2 colblocks
    const dim3 gE(2, Ee / 128);                 // 1 output x 2 colblocks
    const int  bFlash = (Nn * 32 + 255) / 256;
    const int  bCvt = (Nn * DD / 4 + 255) / 256;
    const int  NB = (Nn + 255) / 256;

    // ================= fork =================
    cudaEventRecord(evRoot, 0);
    cudaStreamWaitEvent(sB, evRoot, 0);

    // sB: edge-side prep + CSR + edge GEMMs
    tsplit_w16<<<128, 256, 0, sB>>>(W1[3], wef, 128);
    tsplit_w16<<<128, 256, 0, sB>>>(W2[3], wef + 32768, 128);
    csr_zero<<<NB, 256, 0, sB>>>();
    csr_count<<<(Ee + 255) / 256, 256, 0, sB>>>(ei);
    csr_scan_local<<<NB, 256, 0, sB>>>();
    csr_scan_bsum<<<1, 256, 0, sB>>>(NB);
    csr_finalize<<<NB, 256, 0, sB>>>();
    csr_fill<<<(Ee + 255) / 256, 256, 0, sB>>>(ei);
    cvt_f16<0><<<(int)(((size_t)Ee * EDD / 4 + 255) / 256), 256, 0, sB>>>(
        ea, eaf, (size_t)Ee * EDD / 4);
    gemm_multi<<<gE, 256, GEMMF_SMEM, sB>>>(Ee, 128, eaf, wef, adj,
        e1, e1, e1, nullptr, b1[3], b1[3], b1[3], b1[3]);
    cudaEventRecord(evE1, sB);
    gemm_multi<<<gE, 256, GEMMF_SMEM, sB>>>(Ee, 128, eaf, wef + 32768, adj,
        e2, e2, e2, nullptr, b2[3], b2[3], b2[3], b2[3]);
    cudaEventRecord(evE2, sB);

    // main: node-side prep (Q,K,V,S weights -> fused K-major fp16)
    const float* nodeW1[4] = { W1[0], W1[1], W1[2], W1[4] };
    const float* nodeW2[4] = { W2[0], W2[1], W2[2], W2[4] };
    for (int s = 0; s < 4; s++) {
        tsplit_w16<<<256, 256>>>(nodeW1[s], wqkvs + (size_t)s * 65536, 256);
        tsplit_w16<<<256, 256>>>(nodeW2[s], wqkvs + 262144 + (size_t)s * 65536, 256);
    }
    cvt_f16<0><<<bCvt, 256>>>(x, xf, (size_t)Nn * DD / 4);

    // layer 1: Q,K,V fp16 + S fp32 -> h, one launch
    gemm_multi<<<gQKVS, 256, GEMMF_SMEM>>>(Nn, 256, xf, wqkvs, nullptr,
        q, k, v, h, b1[0], b1[1], b1[2], b1[4]);

    cudaStreamWaitEvent(0, evE1, 0);
    flash_agg<<<bFlash, 256>>>(q, k, v, e1, h);
    cvt_f16<1><<<bCvt, 256>>>(h, xf, (size_t)Nn * DD / 4);

    // layer 2: Q,K,V fp16 + S fp32 -> out
    gemm_multi<<<gQKVS, 256, GEMMF_SMEM>>>(Nn, 256, xf, wqkvs + 262144, nullptr,
        q, k, v, out, b2[0], b2[1], b2[2], b2[4]);

    cudaStreamWaitEvent(0, evE2, 0);
    flash_agg<<<bFlash, 256>>>(q, k, v, e2, out);
}

// round 16
// speedup vs baseline: 1.1716x; 1.0360x over previous
#include <cuda_runtime.h>
#include <cuda_fp16.h>
#include <math.h>
#include <math_constants.h>
#include <cstdint>

#define Nn   50000
#define Ee   800000
#define DD   256
#define EDD  128
#define Hh   4

// ================= scratch (device globals) =================
__device__ __half g_q[Nn * DD];
__device__ __half g_k[Nn * DD];
__device__ __half g_v[Nn * DD];
__device__ float  g_h[Nn * DD];
__device__ __half g_e1[(size_t)Ee * DD];
__device__ __half g_e2[(size_t)Ee * DD];
// CSR for dst-grouped edges
__device__ int g_deg[Nn];
__device__ int g_cursor[Nn];
__device__ int g_loc[Nn];
__device__ int g_bsum[256];
__device__ int g_rowptr[Nn + 1];
__device__ int g_adj[Ee];
__device__ int g_srcp[Ee];
__device__ int g_ctr[2];                  // flash work-stealing counters
// operands
__device__ __half g_xf16[Nn * DD];
__device__ __half g_eaf16[(size_t)Ee * EDD];
__device__ __half g_wqkvs16[2 * 1024 * 256];   // fused Q,K,V,S fp16 K-major
__device__ __half g_wef16[2 * 256 * 128];      // edge weights fp16 K-major

// ================= PTX helpers =================
__device__ __forceinline__ uint32_t smem_u32(const void* p) {
    uint32_t a;
    asm("{ .reg .u64 t; cvta.to.shared.u64 t, %1; cvt.u32.u64 %0, t; }"
        : "=r"(a) : "l"(p));
    return a;
}
__device__ __forceinline__ void ldsm_x4(uint32_t* r, uint32_t a) {
    asm volatile("ldmatrix.sync.aligned.m8n8.x4.shared.b16 {%0,%1,%2,%3}, [%4];"
        : "=r"(r[0]), "=r"(r[1]), "=r"(r[2]), "=r"(r[3]) : "r"(a));
}
__device__ __forceinline__ void ldsm_x2(uint32_t* r, uint32_t a) {
    asm volatile("ldmatrix.sync.aligned.m8n8.x2.shared.b16 {%0,%1}, [%2];"
        : "=r"(r[0]), "=r"(r[1]) : "r"(a));
}
__device__ __forceinline__ void mma_f16(float* d, const uint32_t* a, const uint32_t* b) {
    asm volatile("mma.sync.aligned.m16n8k16.row.col.f32.f16.f16.f32 "
        "{%0,%1,%2,%3}, {%4,%5,%6,%7}, {%8,%9}, {%0,%1,%2,%3};"
        : "+f"(d[0]), "+f"(d[1]), "+f"(d[2]), "+f"(d[3])
        : "r"(a[0]), "r"(a[1]), "r"(a[2]), "r"(a[3]), "r"(b[0]), "r"(b[1]));
}
__device__ __forceinline__ void cpa16(uint32_t dst, const void* src, int sz) {
    asm volatile("cp.async.cg.shared.global [%0], [%1], 16, %2;"
        :: "r"(dst), "l"(src), "r"(sz) : "memory");
}
#define CP_COMMIT() asm volatile("cp.async.commit_group;" ::: "memory")
#define CP_WAIT1()  asm volatile("cp.async.wait_group 1;" ::: "memory")
#define CP_WAIT0()  asm volatile("cp.async.wait_group 0;" ::: "memory")

// ============ fp16 GEMM, up to 4 routed outputs (0-2 fp16, 3 fp32) ============
#define PAD 40
#define STG_F 20480
#define OFF_FB 10240
#define GEMMF_SMEM (2 * STG_F)

__global__ __launch_bounds__(256, 2) void gemm_multi(
    int M, int K,
    const __half* __restrict__ A, const __half* __restrict__ W,
    const int* __restrict__ rowmap,
    __half* c0, __half* c1, __half* c2, float* c3,
    const float* b0, const float* b1, const float* b2, const float* b3)
{
    extern __shared__ char sm[];
    const uint32_t sb = smem_u32(sm);

    const int tid  = threadIdx.x;
    const int lane = tid & 31;
    const int wid  = tid >> 5;
    const int wm   = wid >> 2;
    const int wn   = wid & 3;
    const int row0 = blockIdx.y * 128;

    __half* const houts[3]       = { c0, c1, c2 };
    const float* const biases[4] = { b0, b1, b2, b3 };
    const int    outIdx = blockIdx.x >> 1;
    const float* bias   = biases[outIdx];
    const int    colb   = (blockIdx.x & 1) * 128;
    const int    nW0    = outIdx * 256 + colb;

    const int lr  = tid >> 1;
    const int lcb = (tid & 1) * 16;
    const int grA = row0 + lr;
    const int okA = (grA < M) ? 16 : 0;
    int arow = okA ? grA : 0;
    if (rowmap) arow = rowmap[arow];
    const char* pA = (const char*)(A + (size_t)arow * K + lcb);
    const char* pB = (const char*)(W + (size_t)(nW0 + lr) * K + lcb);
    const uint32_t dstA = sb + (uint32_t)(lr * 80 + (tid & 1) * 32);

    const int nchunk = K >> 5;

    const int aRow    = lane & 15;
    const int aColSel = (lane >> 4) * 8;
    const int bRow    = lane & 7;
    const int bColSel = ((lane >> 3) & 1) * 8;

    float acc[4][4][4];
    #pragma unroll
    for (int i = 0; i < 4; i++)
        #pragma unroll
        for (int j = 0; j < 4; j++)
            #pragma unroll
            for (int t = 0; t < 4; t++) acc[i][j][t] = 0.f;

    {
        cpa16(dstA,                pA,      okA);
        cpa16(dstA + 16,           pA + 16, okA);
        cpa16(dstA + OFF_FB,       pB,      16);
        cpa16(dstA + OFF_FB + 16,  pB + 16, 16);
        CP_COMMIT();
    }

    for (int c = 0; c < nchunk; c++) {
        if (c + 1 < nchunk) {
            const uint32_t d = dstA + ((c + 1) & 1) * STG_F;
            const int go = (c + 1) * 64;
            cpa16(d,               pA + go,      okA);
            cpa16(d + 16,          pA + go + 16, okA);
            cpa16(d + OFF_FB,      pB + go,      16);
            cpa16(d + OFF_FB + 16, pB + go + 16, 16);
            CP_COMMIT();
            CP_WAIT1();
        } else {
            CP_WAIT0();
        }
        __syncthreads();

        const uint32_t sbase = sb + (c & 1) * STG_F;
        #pragma unroll
        for (int ks = 0; ks < 2; ks++) {
            const int kb = ks * 16;
            uint32_t ah[4][4], bh[4][2];
            #pragma unroll
            for (int mt = 0; mt < 4; mt++) {
                const uint32_t off = sbase +
                    (uint32_t)((wm * 64 + mt * 16 + aRow) * PAD + kb + aColSel) * 2;
                ldsm_x4(ah[mt], off);
            }
            #pragma unroll
            for (int nt = 0; nt < 4; nt++) {
                const uint32_t off = sbase + OFF_FB +
                    (uint32_t)((wn * 32 + nt * 8 + bRow) * PAD + kb + bColSel) * 2;
                ldsm_x2(bh[nt], off);
            }
            #pragma unroll
            for (int mt = 0; mt < 4; mt++)
                #pragma unroll
                for (int nt = 0; nt < 4; nt++)
                    mma_f16(acc[mt][nt], ah[mt], bh[nt]);
        }
        __syncthreads();
    }

    if (outIdx < 3) {
        __half* C = houts[outIdx];
        #pragma unroll
        for (int mt = 0; mt < 4; mt++) {
            const int r = row0 + wm * 64 + mt * 16 + (lane >> 2);
            #pragma unroll
            for (int nt = 0; nt < 4; nt++) {
                const int c = colb + wn * 32 + nt * 8 + (lane & 3) * 2;
                if (r < M)
                    *(__half2*)(C + (size_t)r * 256 + c) =
                        __floats2half2_rn(acc[mt][nt][0] + bias[c],
                                          acc[mt][nt][1] + bias[c + 1]);
                if (r + 8 < M)
                    *(__half2*)(C + (size_t)(r + 8) * 256 + c) =
                        __floats2half2_rn(acc[mt][nt][2] + bias[c],
                                          acc[mt][nt][3] + bias[c + 1]);
            }
        }
    } else {
        #pragma unroll
        for (int mt = 0; mt < 4; mt++) {
            const int r = row0 + wm * 64 + mt * 16 + (lane >> 2);
            #pragma unroll
            for (int nt = 0; nt < 4; nt++) {
                const int c = colb + wn * 32 + nt * 8 + (lane & 3) * 2;
                if (r < M) {
                    float2 o = make_float2(acc[mt][nt][0] + bias[c],
                                           acc[mt][nt][1] + bias[c + 1]);
                    *(float2*)(c3 + (size_t)r * 256 + c) = o;
                }
                if (r + 8 < M) {
                    float2 o = make_float2(acc[mt][nt][2] + bias[c],
                                           acc[mt][nt][3] + bias[c + 1]);
                    *(float2*)(c3 + (size_t)(r + 8) * 256 + c) = o;
                }
            }
        }
    }
}

// ======== weight prep: K-major fp16 transpose ========
__global__ void tsplit_w16(const float* __restrict__ W, __half* __restrict__ wt, int K)
{
    const int i = blockIdx.x * blockDim.x + threadIdx.x;
    if (i < K * 256) {
        const int k = i >> 8, n = i & 255;
        wt[(size_t)n * K + k] = __float2half(W[i]);
    }
}

// fp32 -> fp16, optional relu
template <int RELU>
__global__ void cvt_f16(const float* __restrict__ in, __half* __restrict__ o, size_t n4)
{
    const size_t i = (size_t)blockIdx.x * blockDim.x + threadIdx.x;
    if (i >= n4) return;
    float4 v = ((const float4*)in)[i];
    if (RELU) {
        v.x = fmaxf(v.x, 0.f); v.y = fmaxf(v.y, 0.f);
        v.z = fmaxf(v.z, 0.f); v.w = fmaxf(v.w, 0.f);
    }
    ((__half2*)o)[2 * i]     = __floats2half2_rn(v.x, v.y);
    ((__half2*)o)[2 * i + 1] = __floats2half2_rn(v.z, v.w);
}

// ================= CSR build =================
__global__ void csr_zero()
{
    const int i = blockIdx.x * blockDim.x + threadIdx.x;
    if (i < Nn) { g_deg[i] = 0; g_cursor[i] = 0; }
    if (i == 0) { g_ctr[0] = 0; g_ctr[1] = 0; }
}
__global__ void csr_count(const int* __restrict__ ei)
{
    const int i = blockIdx.x * blockDim.x + threadIdx.x;
    if (i < Ee) atomicAdd(&g_deg[ei[Ee + i]], 1);
}
__global__ void csr_scan_local()
{
    __shared__ int s[256];
    const int tid = threadIdx.x;
    const int i = blockIdx.x * 256 + tid;
    const int v = (i < Nn) ? g_deg[i] : 0;
    s[tid] = v; __syncthreads();
    for (int off = 1; off < 256; off <<= 1) {
        const int t = (tid >= off) ? s[tid - off] : 0;
        __syncthreads();
        s[tid] += t;
        __syncthreads();
    }
    if (i < Nn) g_loc[i] = s[tid] - v;
    if (tid == 255) g_bsum[blockIdx.x] = s[255];
}
__global__ void csr_scan_bsum(int nb)
{
    __shared__ int s[256];
    const int t = threadIdx.x;
    const int v = (t < nb) ? g_bsum[t] : 0;
    s[t] = v; __syncthreads();
    for (int off = 1; off < 256; off <<= 1) {
        const int u = (t >= off) ? s[t - off] : 0;
        __syncthreads();
        s[t] += u;
        __syncthreads();
    }
    if (t < nb) g_bsum[t] = s[t] - v;
}
__global__ void csr_finalize()
{
    const int i = blockIdx.x * blockDim.x + threadIdx.x;
    if (i < Nn) g_rowptr[i] = g_loc[i] + g_bsum[i >> 8];
    if (i == 0) g_rowptr[Nn] = Ee;
}
__global__ void csr_fill(const int* __restrict__ ei)
{
    const int eid = blockIdx.x * blockDim.x + threadIdx.x;
    if (eid < Ee) {
        const int src = ei[eid];
        const int dst = ei[Ee + eid];
        const int p = atomicAdd(&g_cursor[dst], 1);
        const int pos = g_rowptr[dst] + p;
        g_adj[pos]  = eid;
        g_srcp[pos] = src;
    }
}

// ====== flash softmax + aggregate: persistent warps, work-stealing ======
__global__ __launch_bounds__(256) void flash_agg(
    const __half* __restrict__ q, const __half* __restrict__ k,
    const __half* __restrict__ v, const __half* __restrict__ e,
    float* __restrict__ out, int* __restrict__ ctr)
{
    const int lane = threadIdx.x & 31;
    const int co = lane * 8;

    for (;;) {
        int node;
        if (lane == 0) node = atomicAdd(ctr, 1);
        node = __shfl_sync(0xffffffffu, node, 0);
        if (node >= Nn) return;

        const int beg = g_rowptr[node];
        const int end = g_rowptr[node + 1];
        if (beg == end) continue;

        float qf[8];
        {
            uint4 u = *(const uint4*)(q + (size_t)node * DD + co);
            const __half2* h = (const __half2*)&u;
            #pragma unroll
            for (int i = 0; i < 4; i++) {
                float2 t = __half22float2(h[i]);
                qf[2 * i] = t.x; qf[2 * i + 1] = t.y;
            }
        }

        float m = -CUDART_INF_F, d = 0.f;
        float a[8];
        #pragma unroll
        for (int i = 0; i < 8; i++) a[i] = 0.f;

        int src = g_srcp[beg];
        uint4 ue = *(const uint4*)(e + (size_t)beg * DD + co);
        uint4 uk = *(const uint4*)(k + (size_t)src * DD + co);
        uint4 uv = *(const uint4*)(v + (size_t)src * DD + co);

        for (int idx = beg; idx < end; idx++) {
            const uint4 ce = ue, ck = uk, cv = uv;
            if (idx + 1 < end) {
                const int s2 = g_srcp[idx + 1];
                ue = *(const uint4*)(e + (size_t)(idx + 1) * DD + co);
                uk = *(const uint4*)(k + (size_t)s2 * DD + co);
                uv = *(const uint4*)(v + (size_t)s2 * DD + co);
            }

            const __half2* eh = (const __half2*)&ce;
            const __half2* kh = (const __half2*)&ck;
            const __half2* vh = (const __half2*)&cv;

            float2 kef[4];
            #pragma unroll
            for (int i = 0; i < 4; i++)
                kef[i] = __half22float2(__hadd2(kh[i], eh[i]));
            float dot = 0.f;
            #pragma unroll
            for (int i = 0; i < 4; i++) {
                dot = fmaf(qf[2 * i],     kef[i].x, dot);
                dot = fmaf(qf[2 * i + 1], kef[i].y, dot);
            }
            dot += __shfl_xor_sync(0xffffffffu, dot, 1);
            dot += __shfl_xor_sync(0xffffffffu, dot, 2);
            dot += __shfl_xor_sync(0xffffffffu, dot, 4);
            const float al = dot * 0.125f;

            const float mn = fmaxf(m, al);
            const float sc = __expf(m - mn);
            const float w  = __expf(al - mn);
            d = d * sc + w;
            #pragma unroll
            for (int i = 0; i < 4; i++) {
                float2 vef = __half22float2(__hadd2(vh[i], eh[i]));
                a[2 * i]     = fmaf(vef.x, w, a[2 * i] * sc);
                a[2 * i + 1] = fmaf(vef.y, w, a[2 * i + 1] * sc);
            }
            m = mn;
        }

        const float inv = 1.f / (d + 1e-16f);
        float* op = out + (size_t)node * DD + co;
        float4 o0 = *(float4*)op, o1 = *(float4*)(op + 4);
        o0.x += a[0] * inv; o0.y += a[1] * inv;
        o0.z += a[2] * inv; o0.w += a[3] * inv;
        o1.x += a[4] * inv; o1.y += a[5] * inv;
        o1.z += a[6] * inv; o1.w += a[7] * inv;
        *(float4*)op       = o0;
        *(float4*)(op + 4) = o1;
    }
}

// ================= host driver =================
static void* symaddr(const void* sym)
{
    void* p = nullptr;
    cudaGetSymbolAddress(&p, sym);
    return p;
}

extern "C" void kernel_launch(void* const* d_in, const int* in_sizes, int n_in,
                              void* d_out, int out_size)
{
    const float* x  = (const float*)d_in[0];
    const int*   ei = (const int*)d_in[1];
    const float* ea = (const float*)d_in[2];
    const float* W1[5] = { (const float*)d_in[3],  (const float*)d_in[5],
                           (const float*)d_in[7],  (const float*)d_in[9],
                           (const float*)d_in[11] };
    const float* b1[5] = { (const float*)d_in[4],  (const float*)d_in[6],
                           (const float*)d_in[8],  (const float*)d_in[10],
                           (const float*)d_in[12] };
    const float* W2[5] = { (const float*)d_in[13], (const float*)d_in[15],
                           (const float*)d_in[17], (const float*)d_in[19],
                           (const float*)d_in[21] };
    const float* b2[5] = { (const float*)d_in[14], (const float*)d_in[16],
                           (const float*)d_in[18], (const float*)d_in[20],
                           (const float*)d_in[22] };

    static __half *q = nullptr, *k, *v, *e1, *e2, *eaf, *wef, *wqkvs, *xf;
    static float *h;
    static int *adj, *ctr;
    static cudaStream_t sB;
    static cudaEvent_t evRoot, evE1, evE2;
    if (!q) {
        q  = (__half*)symaddr(g_q);  k  = (__half*)symaddr(g_k);
        v  = (__half*)symaddr(g_v);  h  = (float*)symaddr(g_h);
        e1 = (__half*)symaddr(g_e1); e2 = (__half*)symaddr(g_e2);
        eaf = (__half*)symaddr(g_eaf16); wef = (__half*)symaddr(g_wef16);
        wqkvs = (__half*)symaddr(g_wqkvs16); xf = (__half*)symaddr(g_xf16);
        adj = (int*)symaddr(g_adj);
        ctr = (int*)symaddr(g_ctr);
        cudaFuncSetAttribute(gemm_multi,
            cudaFuncAttributeMaxDynamicSharedMemorySize, GEMMF_SMEM);
        cudaStreamCreateWithFlags(&sB, cudaStreamNonBlocking);
        cudaEventCreateWithFlags(&evRoot, cudaEventDisableTiming);
        cudaEventCreateWithFlags(&evE1,   cudaEventDisableTiming);
        cudaEventCreateWithFlags(&evE2,   cudaEventDisableTiming);
    }
    float* out = (float*)d_out;

    const dim3 gQKVS(8, (Nn + 127) / 128);
    const dim3 gE(2, Ee / 128);
    const int  bFlash = 1184;                  // persistent blocks (8 warps each)
    const int  bCvt = (Nn * DD / 4 + 255) / 256;
    const int  NB = (Nn + 255) / 256;

    // ================= fork =================
    cudaEventRecord(evRoot, 0);
    cudaStreamWaitEvent(sB, evRoot, 0);

    // sB: edge-side prep + CSR + edge GEMMs
    tsplit_w16<<<128, 256, 0, sB>>>(W1[3], wef, 128);
    tsplit_w16<<<128, 256, 0, sB>>>(W2[3], wef + 32768, 128);
    csr_zero<<<NB, 256, 0, sB>>>();
    csr_count<<<(Ee + 255) / 256, 256, 0, sB>>>(ei);
    csr_scan_local<<<NB, 256, 0, sB>>>();
    csr_scan_bsum<<<1, 256, 0, sB>>>(NB);
    csr_finalize<<<NB, 256, 0, sB>>>();
    csr_fill<<<(Ee + 255) / 256, 256, 0, sB>>>(ei);
    cvt_f16<0><<<(int)(((size_t)Ee * EDD / 4 + 255) / 256), 256, 0, sB>>>(
        ea, eaf, (size_t)Ee * EDD / 4);
    gemm_multi<<<gE, 256, GEMMF_SMEM, sB>>>(Ee, 128, eaf, wef, adj,
        e1, e1, e1, nullptr, b1[3], b1[3], b1[3], b1[3]);
    cudaEventRecord(evE1, sB);
    gemm_multi<<<gE, 256, GEMMF_SMEM, sB>>>(Ee, 128, eaf, wef + 32768, adj,
        e2, e2, e2, nullptr, b2[3], b2[3], b2[3], b2[3]);
    cudaEventRecord(evE2, sB);

    // main: node-side prep (Q,K,V,S weights -> fused K-major fp16)
    const float* nodeW1[4] = { W1[0], W1[1], W1[2], W1[4] };
    const float* nodeW2[4] = { W2[0], W2[1], W2[2], W2[4] };
    for (int s = 0; s < 4; s++) {
        tsplit_w16<<<256, 256>>>(nodeW1[s], wqkvs + (size_t)s * 65536, 256);
        tsplit_w16<<<256, 256>>>(nodeW2[s], wqkvs + 262144 + (size_t)s * 65536, 256);
    }
    cvt_f16<0><<<bCvt, 256>>>(x, xf, (size_t)Nn * DD / 4);

    // layer 1: Q,K,V fp16 + S fp32 -> h
    gemm_multi<<<gQKVS, 256, GEMMF_SMEM>>>(Nn, 256, xf, wqkvs, nullptr,
        q, k, v, h, b1[0], b1[1], b1[2], b1[4]);

    cudaStreamWaitEvent(0, evE1, 0);
    flash_agg<<<bFlash, 256>>>(q, k, v, e1, h, ctr);
    cvt_f16<1><<<bCvt, 256>>>(h, xf, (size_t)Nn * DD / 4);

    // layer 2: Q,K,V fp16 + S fp32 -> out
    gemm_multi<<<gQKVS, 256, GEMMF_SMEM>>>(Nn, 256, xf, wqkvs + 262144, nullptr,
        q, k, v, out, b2[0], b2[1], b2[2], b2[4]);

    cudaStreamWaitEvent(0, evE2, 0);
    flash_agg<<<bFlash, 256>>>(q, k, v, e2, out, ctr + 1);
}

// round 17
// speedup vs baseline: 1.2596x; 1.0751x over previous
#include <cuda_runtime.h>
#include <cuda_fp16.h>
#include <math.h>
#include <math_constants.h>
#include <cstdint>

#define Nn   50000
#define Ee   800000
#define DD   256
#define EDD  128

// ================= scratch (device globals) =================
__device__ __half g_q[Nn * DD];
__device__ __half g_k[Nn * DD];
__device__ __half g_v[Nn * DD];
__device__ float  g_h[Nn * DD];
__device__ __half g_t[Nn * 512];               // T = per-head We^T q   [N,4,128]
__device__ __half g_aea[Nn * 512];             // alpha-weighted ea agg [N,4,128]
__device__ __half g_eas[(size_t)Ee * EDD];     // dst-sorted ea fp16
// CSR
__device__ int g_deg[Nn];
__device__ int g_cursor[Nn];
__device__ int g_loc[Nn];
__device__ int g_bsum[256];
__device__ int g_rowptr[Nn + 1];
__device__ int g_adj[Ee];
__device__ int g_srcp[Ee];
__device__ int g_ctr[2];
// weights
__device__ __half g_xf16[Nn * DD];
__device__ __half g_wqkvs16[2 * 1024 * 256];   // fused Q,K,V,S fp16 K-major
__device__ __half g_wbdt[2 * 512 * 256];       // T-GEMM block-diag weights
__device__ __half g_wbdp[2 * 256 * 512];       // proj-GEMM block-diag weights

// ================= PTX helpers =================
__device__ __forceinline__ uint32_t smem_u32(const void* p) {
    uint32_t a;
    asm("{ .reg .u64 t; cvta.to.shared.u64 t, %1; cvt.u32.u64 %0, t; }"
        : "=r"(a) : "l"(p));
    return a;
}
__device__ __forceinline__ void ldsm_x4(uint32_t* r, uint32_t a) {
    asm volatile("ldmatrix.sync.aligned.m8n8.x4.shared.b16 {%0,%1,%2,%3}, [%4];"
        : "=r"(r[0]), "=r"(r[1]), "=r"(r[2]), "=r"(r[3]) : "r"(a));
}
__device__ __forceinline__ void ldsm_x2(uint32_t* r, uint32_t a) {
    asm volatile("ldmatrix.sync.aligned.m8n8.x2.shared.b16 {%0,%1}, [%2];"
        : "=r"(r[0]), "=r"(r[1]) : "r"(a));
}
__device__ __forceinline__ void mma_f16(float* d, const uint32_t* a, const uint32_t* b) {
    asm volatile("mma.sync.aligned.m16n8k16.row.col.f32.f16.f16.f32 "
        "{%0,%1,%2,%3}, {%4,%5,%6,%7}, {%8,%9}, {%0,%1,%2,%3};"
        : "+f"(d[0]), "+f"(d[1]), "+f"(d[2]), "+f"(d[3])
        : "r"(a[0]), "r"(a[1]), "r"(a[2]), "r"(a[3]), "r"(b[0]), "r"(b[1]));
}
__device__ __forceinline__ void cpa16(uint32_t dst, const void* src, int sz) {
    asm volatile("cp.async.cg.shared.global [%0], [%1], 16, %2;"
        :: "r"(dst), "l"(src), "r"(sz) : "memory");
}
#define CP_COMMIT() asm volatile("cp.async.commit_group;" ::: "memory")
#define CP_WAIT1()  asm volatile("cp.async.wait_group 1;" ::: "memory")
#define CP_WAIT0()  asm volatile("cp.async.wait_group 0;" ::: "memory")

// ============ fp16 GEMM, 4 routed outputs (0-2 fp16, 3 fp32), stride 256 ======
#define PAD 40
#define STG_F 20480
#define OFF_FB 10240
#define GEMMF_SMEM (2 * STG_F)

__global__ __launch_bounds__(256, 2) void gemm_multi(
    int M, int K,
    const __half* __restrict__ A, const __half* __restrict__ W,
    __half* c0, __half* c1, __half* c2, float* c3,
    const float* b0, const float* b1, const float* b2, const float* b3)
{
    extern __shared__ char sm[];
    const uint32_t sb = smem_u32(sm);

    const int tid  = threadIdx.x;
    const int lane = tid & 31;
    const int wid  = tid >> 5;
    const int wm   = wid >> 2;
    const int wn   = wid & 3;
    const int row0 = blockIdx.y * 128;

    __half* const houts[3]       = { c0, c1, c2 };
    const float* const biases[4] = { b0, b1, b2, b3 };
    const int    outIdx = blockIdx.x >> 1;
    const float* bias   = biases[outIdx];
    const int    colb   = (blockIdx.x & 1) * 128;
    const int    nW0    = outIdx * 256 + colb;

    const int lr  = tid >> 1;
    const int lcb = (tid & 1) * 16;
    const int grA = row0 + lr;
    const int okA = (grA < M) ? 16 : 0;
    const int arow = okA ? grA : 0;
    const char* pA = (const char*)(A + (size_t)arow * K + lcb);
    const char* pB = (const char*)(W + (size_t)(nW0 + lr) * K + lcb);
    const uint32_t dstA = sb + (uint32_t)(lr * 80 + (tid & 1) * 32);

    const int nchunk = K >> 5;

    const int aRow    = lane & 15;
    const int aColSel = (lane >> 4) * 8;
    const int bRow    = lane & 7;
    const int bColSel = ((lane >> 3) & 1) * 8;

    float acc[4][4][4];
    #pragma unroll
    for (int i = 0; i < 4; i++)
        #pragma unroll
        for (int j = 0; j < 4; j++)
            #pragma unroll
            for (int t = 0; t < 4; t++) acc[i][j][t] = 0.f;

    {
        cpa16(dstA,                pA,      okA);
        cpa16(dstA + 16,           pA + 16, okA);
        cpa16(dstA + OFF_FB,       pB,      16);
        cpa16(dstA + OFF_FB + 16,  pB + 16, 16);
        CP_COMMIT();
    }

    for (int c = 0; c < nchunk; c++) {
        if (c + 1 < nchunk) {
            const uint32_t d = dstA + ((c + 1) & 1) * STG_F;
            const int go = (c + 1) * 64;
            cpa16(d,               pA + go,      okA);
            cpa16(d + 16,          pA + go + 16, okA);
            cpa16(d + OFF_FB,      pB + go,      16);
            cpa16(d + OFF_FB + 16, pB + go + 16, 16);
            CP_COMMIT();
            CP_WAIT1();
        } else {
            CP_WAIT0();
        }
        __syncthreads();

        const uint32_t sbase = sb + (c & 1) * STG_F;
        #pragma unroll
        for (int ks = 0; ks < 2; ks++) {
            const int kb = ks * 16;
            uint32_t ah[4][4], bh[4][2];
            #pragma unroll
            for (int mt = 0; mt < 4; mt++) {
                const uint32_t off = sbase +
                    (uint32_t)((wm * 64 + mt * 16 + aRow) * PAD + kb + aColSel) * 2;
                ldsm_x4(ah[mt], off);
            }
            #pragma unroll
            for (int nt = 0; nt < 4; nt++) {
                const uint32_t off = sbase + OFF_FB +
                    (uint32_t)((wn * 32 + nt * 8 + bRow) * PAD + kb + bColSel) * 2;
                ldsm_x2(bh[nt], off);
            }
            #pragma unroll
            for (int mt = 0; mt < 4; mt++)
                #pragma unroll
                for (int nt = 0; nt < 4; nt++)
                    mma_f16(acc[mt][nt], ah[mt], bh[nt]);
        }
        __syncthreads();
    }

    if (outIdx < 3) {
        __half* C = houts[outIdx];
        #pragma unroll
        for (int mt = 0; mt < 4; mt++) {
            const int r = row0 + wm * 64 + mt * 16 + (lane >> 2);
            #pragma unroll
            for (int nt = 0; nt < 4; nt++) {
                const int c = colb + wn * 32 + nt * 8 + (lane & 3) * 2;
                if (r < M)
                    *(__half2*)(C + (size_t)r * 256 + c) =
                        __floats2half2_rn(acc[mt][nt][0] + bias[c],
                                          acc[mt][nt][1] + bias[c + 1]);
                if (r + 8 < M)
                    *(__half2*)(C + (size_t)(r + 8) * 256 + c) =
                        __floats2half2_rn(acc[mt][nt][2] + bias[c],
                                          acc[mt][nt][3] + bias[c + 1]);
            }
        }
    } else {
        #pragma unroll
        for (int mt = 0; mt < 4; mt++) {
            const int r = row0 + wm * 64 + mt * 16 + (lane >> 2);
            #pragma unroll
            for (int nt = 0; nt < 4; nt++) {
                const int c = colb + wn * 32 + nt * 8 + (lane & 3) * 2;
                if (r < M) {
                    float2 o = make_float2(acc[mt][nt][0] + bias[c],
                                           acc[mt][nt][1] + bias[c + 1]);
                    *(float2*)(c3 + (size_t)r * 256 + c) = o;
                }
                if (r + 8 < M) {
                    float2 o = make_float2(acc[mt][nt][2] + bias[c],
                                           acc[mt][nt][3] + bias[c + 1]);
                    *(float2*)(c3 + (size_t)(r + 8) * 256 + c) = o;
                }
            }
        }
    }
}

// ======== single-output fp16 GEMM, arbitrary Nout (grid.x colblocks) =========
// ACC=0: fp16 store (no bias). ACC=1: fp32 accumulate into C.
template <int ACC>
__global__ __launch_bounds__(256, 2) void gemm_single(
    int M, int K, int ldc,
    const __half* __restrict__ A, const __half* __restrict__ W,
    void* __restrict__ Cv)
{
    extern __shared__ char sm[];
    const uint32_t sb = smem_u32(sm);

    const int tid  = threadIdx.x;
    const int lane = tid & 31;
    const int wid  = tid >> 5;
    const int wm   = wid >> 2;
    const int wn   = wid & 3;
    const int row0 = blockIdx.y * 128;
    const int colb = blockIdx.x * 128;

    const int lr  = tid >> 1;
    const int lcb = (tid & 1) * 16;
    const int grA = row0 + lr;
    const int okA = (grA < M) ? 16 : 0;
    const int arow = okA ? grA : 0;
    const char* pA = (const char*)(A + (size_t)arow * K + lcb);
    const char* pB = (const char*)(W + (size_t)(colb + lr) * K + lcb);
    const uint32_t dstA = sb + (uint32_t)(lr * 80 + (tid & 1) * 32);

    const int nchunk = K >> 5;

    const int aRow    = lane & 15;
    const int aColSel = (lane >> 4) * 8;
    const int bRow    = lane & 7;
    const int bColSel = ((lane >> 3) & 1) * 8;

    float acc[4][4][4];
    #pragma unroll
    for (int i = 0; i < 4; i++)
        #pragma unroll
        for (int j = 0; j < 4; j++)
            #pragma unroll
            for (int t = 0; t < 4; t++) acc[i][j][t] = 0.f;

    {
        cpa16(dstA,                pA,      okA);
        cpa16(dstA + 16,           pA + 16, okA);
        cpa16(dstA + OFF_FB,       pB,      16);
        cpa16(dstA + OFF_FB + 16,  pB + 16, 16);
        CP_COMMIT();
    }

    for (int c = 0; c < nchunk; c++) {
        if (c + 1 < nchunk) {
            const uint32_t d = dstA + ((c + 1) & 1) * STG_F;
            const int go = (c + 1) * 64;
            cpa16(d,               pA + go,      okA);
            cpa16(d + 16,          pA + go + 16, okA);
            cpa16(d + OFF_FB,      pB + go,      16);
            cpa16(d + OFF_FB + 16, pB + go + 16, 16);
            CP_COMMIT();
            CP_WAIT1();
        } else {
            CP_WAIT0();
        }
        __syncthreads();

        const uint32_t sbase = sb + (c & 1) * STG_F;
        #pragma unroll
        for (int ks = 0; ks < 2; ks++) {
            const int kb = ks * 16;
            uint32_t ah[4][4], bh[4][2];
            #pragma unroll
            for (int mt = 0; mt < 4; mt++) {
                const uint32_t off = sbase +
                    (uint32_t)((wm * 64 + mt * 16 + aRow) * PAD + kb + aColSel) * 2;
                ldsm_x4(ah[mt], off);
            }
            #pragma unroll
            for (int nt = 0; nt < 4; nt++) {
                const uint32_t off = sbase + OFF_FB +
                    (uint32_t)((wn * 32 + nt * 8 + bRow) * PAD + kb + bColSel) * 2;
                ldsm_x2(bh[nt], off);
            }
            #pragma unroll
            for (int mt = 0; mt < 4; mt++)
                #pragma unroll
                for (int nt = 0; nt < 4; nt++)
                    mma_f16(acc[mt][nt], ah[mt], bh[nt]);
        }
        __syncthreads();
    }

    #pragma unroll
    for (int mt = 0; mt < 4; mt++) {
        const int r = row0 + wm * 64 + mt * 16 + (lane >> 2);
        #pragma unroll
        for (int nt = 0; nt < 4; nt++) {
            const int c = colb + wn * 32 + nt * 8 + (lane & 3) * 2;
            if (ACC == 0) {
                __half* C = (__half*)Cv;
                if (r < M)
                    *(__half2*)(C + (size_t)r * ldc + c) =
                        __floats2half2_rn(acc[mt][nt][0], acc[mt][nt][1]);
                if (r + 8 < M)
                    *(__half2*)(C + (size_t)(r + 8) * ldc + c) =
                        __floats2half2_rn(acc[mt][nt][2], acc[mt][nt][3]);
            } else {
                float* C = (float*)Cv;
                if (r < M) {
                    float2 o = *(float2*)(C + (size_t)r * ldc + c);
                    o.x += acc[mt][nt][0]; o.y += acc[mt][nt][1];
                    *(float2*)(C + (size_t)r * ldc + c) = o;
                }
                if (r + 8 < M) {
                    float2 o = *(float2*)(C + (size_t)(r + 8) * ldc + c);
                    o.x += acc[mt][nt][2]; o.y += acc[mt][nt][3];
                    *(float2*)(C + (size_t)(r + 8) * ldc + c) = o;
                }
            }
        }
    }
}

// ======== weight prep ========
__global__ void tsplit_w16(const float* __restrict__ W, __half* __restrict__ wt, int K)
{
    const int i = blockIdx.x * blockDim.x + threadIdx.x;
    if (i < K * 256) {
        const int k = i >> 8, n = i & 255;
        wt[(size_t)n * K + k] = __float2half(W[i]);
    }
}
// block-diag T weights [512,256] K-major: Wt[(g*128+j)*256 + col] = We[j][col]
__global__ void fill_wt(const float* __restrict__ We, __half* __restrict__ Wt)
{
    const int i = blockIdx.x * blockDim.x + threadIdx.x;
    if (i < 128 * 256) {
        const int j = i >> 8, col = i & 255, g = col >> 6;
        Wt[(size_t)(g * 128 + j) * 256 + col] = __float2half(We[i]);
    }
}
// block-diag proj weights [256,512] K-major: Wp[col*512 + g*128 + j] = We[j][col]
__global__ void fill_wp(const float* __restrict__ We, __half* __restrict__ Wp)
{
    const int i = blockIdx.x * blockDim.x + threadIdx.x;
    if (i < 128 * 256) {
        const int j = i >> 8, col = i & 255, g = col >> 6;
        Wp[(size_t)col * 512 + g * 128 + j] = __float2half(We[i]);
    }
}

template <int RELU>
__global__ void cvt_f16(const float* __restrict__ in, __half* __restrict__ o, size_t n4)
{
    const size_t i = (size_t)blockIdx.x * blockDim.x + threadIdx.x;
    if (i >= n4) return;
    float4 v = ((const float4*)in)[i];
    if (RELU) {
        v.x = fmaxf(v.x, 0.f); v.y = fmaxf(v.y, 0.f);
        v.z = fmaxf(v.z, 0.f); v.w = fmaxf(v.w, 0.f);
    }
    ((__half2*)o)[2 * i]     = __floats2half2_rn(v.x, v.y);
    ((__half2*)o)[2 * i + 1] = __floats2half2_rn(v.z, v.w);
}

// gather ea rows into dst-sorted fp16 buffer
__global__ void cvt_sort(const float* __restrict__ ea, __half* __restrict__ eas)
{
    const int warp = (blockIdx.x * blockDim.x + threadIdx.x) >> 5;
    const int lane = threadIdx.x & 31;
    if (warp >= Ee) return;
    const int edge = g_adj[warp];
    float4 v = ((const float4*)(ea + (size_t)edge * EDD))[lane];
    __half2* dst = (__half2*)(eas + (size_t)warp * EDD + lane * 4);
    dst[0] = __floats2half2_rn(v.x, v.y);
    dst[1] = __floats2half2_rn(v.z, v.w);
}

// ================= CSR build =================
__global__ void csr_zero()
{
    const int i = blockIdx.x * blockDim.x + threadIdx.x;
    if (i < Nn) { g_deg[i] = 0; g_cursor[i] = 0; }
    if (i == 0) { g_ctr[0] = 0; g_ctr[1] = 0; }
}
__global__ void csr_count(const int* __restrict__ ei)
{
    const int i = blockIdx.x * blockDim.x + threadIdx.x;
    if (i < Ee) atomicAdd(&g_deg[ei[Ee + i]], 1);
}
__global__ void csr_scan_local()
{
    __shared__ int s[256];
    const int tid = threadIdx.x;
    const int i = blockIdx.x * 256 + tid;
    const int v = (i < Nn) ? g_deg[i] : 0;
    s[tid] = v; __syncthreads();
    for (int off = 1; off < 256; off <<= 1) {
        const int t = (tid >= off) ? s[tid - off] : 0;
        __syncthreads();
        s[tid] += t;
        __syncthreads();
    }
    if (i < Nn) g_loc[i] = s[tid] - v;
    if (tid == 255) g_bsum[blockIdx.x] = s[255];
}
__global__ void csr_scan_bsum(int nb)
{
    __shared__ int s[256];
    const int t = threadIdx.x;
    const int v = (t < nb) ? g_bsum[t] : 0;
    s[t] = v; __syncthreads();
    for (int off = 1; off < 256; off <<= 1) {
        const int u = (t >= off) ? s[t - off] : 0;
        __syncthreads();
        s[t] += u;
        __syncthreads();
    }
    if (t < nb) g_bsum[t] = s[t] - v;
}
__global__ void csr_finalize()
{
    const int i = blockIdx.x * blockDim.x + threadIdx.x;
    if (i < Nn) g_rowptr[i] = g_loc[i] + g_bsum[i >> 8];
    if (i == 0) g_rowptr[Nn] = Ee;
}
__global__ void csr_fill(const int* __restrict__ ei)
{
    const int eid = blockIdx.x * blockDim.x + threadIdx.x;
    if (eid < Ee) {
        const int src = ei[eid];
        const int dst = ei[Ee + eid];
        const int p = atomicAdd(&g_cursor[dst], 1);
        const int pos = g_rowptr[dst] + p;
        g_adj[pos]  = eid;
        g_srcp[pos] = src;
    }
}

// ====== flash v2: e-free attention via T / aea decomposition ======
__global__ __launch_bounds__(256) void flash_v2(
    const __half* __restrict__ q, const __half* __restrict__ k,
    const __half* __restrict__ v, const __half* __restrict__ eas,
    const __half* __restrict__ t, const float* __restrict__ be,
    __half* __restrict__ aea, float* __restrict__ out, int* __restrict__ ctr)
{
    const int lane = threadIdx.x & 31;
    const int co = lane * 8;
    const int g = lane >> 3;
    const int p = lane & 7;
    const int eo = g * 128 + p * 16;          // this lane's T/aea slice

    float beL[8];
    {
        float4 b0 = *(const float4*)(be + co);
        float4 b1 = *(const float4*)(be + co + 4);
        beL[0]=b0.x; beL[1]=b0.y; beL[2]=b0.z; beL[3]=b0.w;
        beL[4]=b1.x; beL[5]=b1.y; beL[6]=b1.z; beL[7]=b1.w;
    }

    for (;;) {
        int node;
        if (lane == 0) node = atomicAdd(ctr, 1);
        node = __shfl_sync(0xffffffffu, node, 0);
        if (node >= Nn) return;

        const int beg = g_rowptr[node];
        const int end = g_rowptr[node + 1];
        __half* aeap = aea + (size_t)node * 512 + eo;
        if (beg == end) {
            ((uint4*)aeap)[0] = make_uint4(0, 0, 0, 0);
            ((uint4*)aeap)[1] = make_uint4(0, 0, 0, 0);
            continue;
        }

        float qf[8];
        {
            uint4 u = *(const uint4*)(q + (size_t)node * DD + co);
            const __half2* hh = (const __half2*)&u;
            #pragma unroll
            for (int i = 0; i < 4; i++) {
                float2 tt = __half22float2(hh[i]);
                qf[2 * i] = tt.x; qf[2 * i + 1] = tt.y;
            }
        }
        float tf[16];
        {
            uint4 u0 = ((const uint4*)(t + (size_t)node * 512 + eo))[0];
            uint4 u1 = ((const uint4*)(t + (size_t)node * 512 + eo))[1];
            const __half2* h0 = (const __half2*)&u0;
            const __half2* h1 = (const __half2*)&u1;
            #pragma unroll
            for (int i = 0; i < 4; i++) {
                float2 a2 = __half22float2(h0[i]);
                float2 b2 = __half22float2(h1[i]);
                tf[2 * i] = a2.x; tf[2 * i + 1] = a2.y;
                tf[8 + 2 * i] = b2.x; tf[9 + 2 * i] = b2.y;
            }
        }
        // qbe = q_h . be_h (reduced over this 8-lane head group)
        float qbe = 0.f;
        #pragma unroll
        for (int i = 0; i < 8; i++) qbe = fmaf(qf[i], beL[i], qbe);
        qbe += __shfl_xor_sync(0xffffffffu, qbe, 1);
        qbe += __shfl_xor_sync(0xffffffffu, qbe, 2);
        qbe += __shfl_xor_sync(0xffffffffu, qbe, 4);

        float m = -CUDART_INF_F, d = 0.f;
        float a[8], ae[16];
        #pragma unroll
        for (int i = 0; i < 8; i++) a[i] = 0.f;
        #pragma unroll
        for (int i = 0; i < 16; i++) ae[i] = 0.f;

        int src = g_srcp[beg];
        uint4 uk = *(const uint4*)(k + (size_t)src * DD + co);
        uint4 uv = *(const uint4*)(v + (size_t)src * DD + co);
        uint4 ue0 = ((const uint4*)(eas + (size_t)beg * EDD + p * 16))[0];
        uint4 ue1 = ((const uint4*)(eas + (size_t)beg * EDD + p * 16))[1];

        for (int idx = beg; idx < end; idx++) {
            const uint4 ck = uk, cv = uv, ce0 = ue0, ce1 = ue1;
            if (idx + 1 < end) {
                const int s2 = g_srcp[idx + 1];
                uk = *(const uint4*)(k + (size_t)s2 * DD + co);
                uv = *(const uint4*)(v + (size_t)s2 * DD + co);
                ue0 = ((const uint4*)(eas + (size_t)(idx + 1) * EDD + p * 16))[0];
                ue1 = ((const uint4*)(eas + (size_t)(idx + 1) * EDD + p * 16))[1];
            }

            const __half2* kh = (const __half2*)&ck;
            const __half2* vh = (const __half2*)&cv;
            const __half2* e0 = (const __half2*)&ce0;
            const __half2* e1 = (const __half2*)&ce1;

            float eaf[16];
            #pragma unroll
            for (int i = 0; i < 4; i++) {
                float2 x0 = __half22float2(e0[i]);
                float2 x1 = __half22float2(e1[i]);
                eaf[2 * i] = x0.x; eaf[2 * i + 1] = x0.y;
                eaf[8 + 2 * i] = x1.x; eaf[9 + 2 * i] = x1.y;
            }

            float partial = 0.f;
            #pragma unroll
            for (int i = 0; i < 4; i++) {
                float2 kf = __half22float2(kh[i]);
                partial = fmaf(qf[2 * i], kf.x, partial);
                partial = fmaf(qf[2 * i + 1], kf.y, partial);
            }
            #pragma unroll
            for (int i = 0; i < 16; i++)
                partial = fmaf(tf[i], eaf[i], partial);
            partial += __shfl_xor_sync(0xffffffffu, partial, 1);
            partial += __shfl_xor_sync(0xffffffffu, partial, 2);
            partial += __shfl_xor_sync(0xffffffffu, partial, 4);
            const float al = (partial + qbe) * 0.125f;

            const float mn = fmaxf(m, al);
            const float sc = __expf(m - mn);
            const float w  = __expf(al - mn);
            d = d * sc + w;
            #pragma unroll
            for (int i = 0; i < 4; i++) {
                float2 vf = __half22float2(vh[i]);
                a[2 * i]     = fmaf(vf.x, w, a[2 * i] * sc);
                a[2 * i + 1] = fmaf(vf.y, w, a[2 * i + 1] * sc);
            }
            #pragma unroll
            for (int i = 0; i < 16; i++)
                ae[i] = fmaf(eaf[i], w, ae[i] * sc);
            m = mn;
        }

        const float inv = 1.f / (d + 1e-16f);
        float* op = out + (size_t)node * DD + co;
        float4 o0 = *(float4*)op, o1 = *(float4*)(op + 4);
        o0.x += a[0] * inv + beL[0]; o0.y += a[1] * inv + beL[1];
        o0.z += a[2] * inv + beL[2]; o0.w += a[3] * inv + beL[3];
        o1.x += a[4] * inv + beL[4]; o1.y += a[5] * inv + beL[5];
        o1.z += a[6] * inv + beL[6]; o1.w += a[7] * inv + beL[7];
        *(float4*)op       = o0;
        *(float4*)(op + 4) = o1;

        __half2 hs[8];
        #pragma unroll
        for (int i = 0; i < 8; i++)
            hs[i] = __floats2half2_rn(ae[2 * i] * inv, ae[2 * i + 1] * inv);
        ((uint4*)aeap)[0] = *(uint4*)&hs[0];
        ((uint4*)aeap)[1] = *(uint4*)&hs[4];
    }
}

// ================= host driver =================
static void* symaddr(const void* sym)
{
    void* p = nullptr;
    cudaGetSymbolAddress(&p, sym);
    return p;
}

extern "C" void kernel_launch(void* const* d_in, const int* in_sizes, int n_in,
                              void* d_out, int out_size)
{
    const float* x  = (const float*)d_in[0];
    const int*   ei = (const int*)d_in[1];
    const float* ea = (const float*)d_in[2];
    const float* W1[5] = { (const float*)d_in[3],  (const float*)d_in[5],
                           (const float*)d_in[7],  (const float*)d_in[9],
                           (const float*)d_in[11] };
    const float* b1[5] = { (const float*)d_in[4],  (const float*)d_in[6],
                           (const float*)d_in[8],  (const float*)d_in[10],
                           (const float*)d_in[12] };
    const float* W2[5] = { (const float*)d_in[13], (const float*)d_in[15],
                           (const float*)d_in[17], (const float*)d_in[19],
                           (const float*)d_in[21] };
    const float* b2[5] = { (const float*)d_in[14], (const float*)d_in[16],
                           (const float*)d_in[18], (const float*)d_in[20],
                           (const float*)d_in[22] };

    static __half *q = nullptr, *k, *v, *eas, *t, *aea, *wqkvs, *wbdt, *wbdp, *xf;
    static float *h;
    static int *ctr;
    static cudaStream_t sB;
    static cudaEvent_t evRoot, evSort;
    if (!q) {
        q   = (__half*)symaddr(g_q);   k   = (__half*)symaddr(g_k);
        v   = (__half*)symaddr(g_v);   h   = (float*)symaddr(g_h);
        eas = (__half*)symaddr(g_eas); t   = (__half*)symaddr(g_t);
        aea = (__half*)symaddr(g_aea);
        wqkvs = (__half*)symaddr(g_wqkvs16);
        wbdt  = (__half*)symaddr(g_wbdt);
        wbdp  = (__half*)symaddr(g_wbdp);
        xf    = (__half*)symaddr(g_xf16);
        ctr   = (int*)symaddr(g_ctr);
        cudaFuncSetAttribute(gemm_multi,
            cudaFuncAttributeMaxDynamicSharedMemorySize, GEMMF_SMEM);
        cudaFuncSetAttribute(gemm_single<0>,
            cudaFuncAttributeMaxDynamicSharedMemorySize, GEMMF_SMEM);
        cudaFuncSetAttribute(gemm_single<1>,
            cudaFuncAttributeMaxDynamicSharedMemorySize, GEMMF_SMEM);
        cudaStreamCreateWithFlags(&sB, cudaStreamNonBlocking);
        cudaEventCreateWithFlags(&evRoot, cudaEventDisableTiming);
        cudaEventCreateWithFlags(&evSort, cudaEventDisableTiming);
    }
    float* out = (float*)d_out;

    const dim3 gQKVS(8, (Nn + 127) / 128);
    const dim3 gT(4, (Nn + 127) / 128);        // Nout=512
    const dim3 gP(2, (Nn + 127) / 128);        // Nout=256
    const int  bFlash = 1184;
    const int  bCvt = (Nn * DD / 4 + 255) / 256;
    const int  NB = (Nn + 255) / 256;

    // ================= fork =================
    cudaEventRecord(evRoot, 0);
    cudaStreamWaitEvent(sB, evRoot, 0);

    // sB: CSR + dst-sorted ea
    csr_zero<<<NB, 256, 0, sB>>>();
    csr_count<<<(Ee + 255) / 256, 256, 0, sB>>>(ei);
    csr_scan_local<<<NB, 256, 0, sB>>>();
    csr_scan_bsum<<<1, 256, 0, sB>>>(NB);
    csr_finalize<<<NB, 256, 0, sB>>>();
    csr_fill<<<(Ee + 255) / 256, 256, 0, sB>>>(ei);
    cvt_sort<<<(Ee * 32 + 255) / 256, 256, 0, sB>>>(ea, eas);
    cudaEventRecord(evSort, sB);

    // main: weight prep
    const float* nodeW1[4] = { W1[0], W1[1], W1[2], W1[4] };
    const float* nodeW2[4] = { W2[0], W2[1], W2[2], W2[4] };
    for (int s = 0; s < 4; s++) {
        tsplit_w16<<<256, 256>>>(nodeW1[s], wqkvs + (size_t)s * 65536, 256);
        tsplit_w16<<<256, 256>>>(nodeW2[s], wqkvs + 262144 + (size_t)s * 65536, 256);
    }
    cudaMemsetAsync(wbdt, 0, 2 * 512 * 256 * sizeof(__half), 0);
    cudaMemsetAsync(wbdp, 0, 2 * 256 * 512 * sizeof(__half), 0);
    fill_wt<<<128, 256>>>(W1[3], wbdt);
    fill_wt<<<128, 256>>>(W2[3], wbdt + 512 * 256);
    fill_wp<<<128, 256>>>(W1[3], wbdp);
    fill_wp<<<128, 256>>>(W2[3], wbdp + 256 * 512);
    cvt_f16<0><<<bCvt, 256>>>(x, xf, (size_t)Nn * DD / 4);

    // layer 1
    gemm_multi<<<gQKVS, 256, GEMMF_SMEM>>>(Nn, 256, xf, wqkvs,
        q, k, v, h, b1[0], b1[1], b1[2], b1[4]);
    gemm_single<0><<<gT, 256, GEMMF_SMEM>>>(Nn, 256, 512, q, wbdt, t);
    cudaStreamWaitEvent(0, evSort, 0);
    flash_v2<<<bFlash, 256>>>(q, k, v, eas, t, b1[3], aea, h, ctr);
    gemm_single<1><<<gP, 256, GEMMF_SMEM>>>(Nn, 512, 256, aea, wbdp, h);
    cvt_f16<1><<<bCvt, 256>>>(h, xf, (size_t)Nn * DD / 4);

    // layer 2
    gemm_multi<<<gQKVS, 256, GEMMF_SMEM>>>(Nn, 256, xf, wqkvs + 262144,
        q, k, v, out, b2[0], b2[1], b2[2], b2[4]);
    gemm_single<0><<<gT, 256, GEMMF_SMEM>>>(Nn, 256, 512, q, wbdt + 512 * 256, t);
    flash_v2<<<bFlash, 256>>>(q, k, v, eas, t, b2[3], aea, out, ctr + 1);
    gemm_single<1><<<gP, 256, GEMMF_SMEM>>>(Nn, 512, 256, aea, wbdp + 256 * 512, out);
}